// round 1
// baseline (speedup 1.0000x reference)
#include <cuda_runtime.h>
#include <cstdint>
#include <math.h>

// Problem constants
#define Bn 32
#define Cn 128
#define Hn 56
#define Wn 56
#define Kn 5
#define CRn 32
#define CEn 512
#define HW 3136          // 56*56
#define PIX_TILE 64      // 3136 = 49*64
#define NPT 49           // pixel tiles per image
#define EPSV 1e-6f

// ---------------- scratch (device globals; no runtime allocation) ----------------
__device__ float g_pooled[Bn * Cn];
__device__ float g_dyn[Bn * Cn * 25];
__device__ float g_conv[(size_t)Bn * Cn * HW];            // 51.4 MB
__device__ float g_gelu[(size_t)Bn * CEn * HW];           // 205.5 MB
__device__ float g_sumsq[Bn * CEn];
__device__ float g_scale[Bn * CEn];

// ---------------- k0: zero GRN accumulator ----------------
__global__ void k_zero() {
    g_sumsq[blockIdx.x * CEn + threadIdx.x] = 0.f;
}

// ---------------- k1: global average pool ----------------
__global__ void k_pool(const float* __restrict__ x) {
    int bc = blockIdx.x;
    const float* p = x + (size_t)bc * HW;
    float s = 0.f;
    for (int i = threadIdx.x; i < HW / 4; i += 256) {
        float4 v = reinterpret_cast<const float4*>(p)[i];
        s += v.x + v.y + v.z + v.w;
    }
    __shared__ float sm[256];
    sm[threadIdx.x] = s;
    __syncthreads();
    for (int o = 128; o > 0; o >>= 1) {
        if (threadIdx.x < o) sm[threadIdx.x] += sm[threadIdx.x + o];
        __syncthreads();
    }
    if (threadIdx.x == 0) g_pooled[bc] = sm[0] * (1.f / (float)HW);
}

// ---------------- k2: fc1 -> LN1 -> fc2 (dyn kernels) ----------------
__global__ void k_fc(const float* __restrict__ w_fc1,
                     const float* __restrict__ ln1w, const float* __restrict__ ln1b,
                     const float* __restrict__ w_fc2) {
    int b = blockIdx.x;
    int t = threadIdx.x;              // 128 threads
    __shared__ float sp[Cn];
    __shared__ float sh[CRn];
    sp[t] = g_pooled[b * Cn + t];
    __syncthreads();
    if (t < 32) {
        const float* wr = w_fc1 + t * Cn;
        float a = 0.f;
        #pragma unroll
        for (int i = 0; i < Cn; i++) a += wr[i] * sp[i];
        float u = a;
        #pragma unroll
        for (int o = 16; o > 0; o >>= 1) u += __shfl_xor_sync(0xffffffffu, u, o);
        u *= (1.f / 32.f);
        float d = a - u;
        float v = d * d;
        #pragma unroll
        for (int o = 16; o > 0; o >>= 1) v += __shfl_xor_sync(0xffffffffu, v, o);
        v *= (1.f / 32.f);
        sh[t] = d * rsqrtf(v + EPSV) * ln1w[t] + ln1b[t];
    }
    __syncthreads();
    for (int i = t; i < Cn * 25; i += 128) {
        const float* wr = w_fc2 + i * CRn;
        float a = 0.f;
        #pragma unroll
        for (int j = 0; j < CRn; j++) a += wr[j] * sh[j];
        g_dyn[b * Cn * 25 + i] = a;
    }
}

// ---------------- k3: dynamic depthwise 5x5 conv ----------------
__global__ void k_conv(const float* __restrict__ x) {
    int bc = blockIdx.x;
    __shared__ float tile[60 * 60];
    const float* xp = x + (size_t)bc * HW;
    for (int i = threadIdx.x; i < 3600; i += 256) {
        int r = i / 60, cc = i % 60;
        int h = r - 2, w = cc - 2;
        tile[i] = (h >= 0 && h < Hn && w >= 0 && w < Wn) ? xp[h * Wn + w] : 0.f;
    }
    float kk[25];
    const float* dp = g_dyn + bc * 25;
    #pragma unroll
    for (int i = 0; i < 25; i++) kk[i] = dp[i];
    __syncthreads();
    float* op = g_conv + (size_t)bc * HW;
    for (int p = threadIdx.x; p < HW; p += 256) {
        int h = p / Wn, w = p % Wn;
        float a = 0.f;
        #pragma unroll
        for (int i = 0; i < 5; i++)
            #pragma unroll
            for (int j = 0; j < 5; j++)
                a += kk[i * 5 + j] * tile[(h + i) * 60 + (w + j)];
        op[p] = a;
    }
}

// ---------------- k4: channel-LN + expand GEMM + gelu + GRN partial sums ----------------
// grid (49, 32), 256 threads, dynamic smem
#define SW_STRIDE 132
__global__ void k_expand(const float* __restrict__ ln2w, const float* __restrict__ ln2b,
                         const float* __restrict__ w_expand) {
    extern __shared__ float sm[];
    float* s_ln  = sm;                         // 128*64
    float* s_w   = s_ln + Cn * PIX_TILE;       // 128*132
    float* s_r1  = s_w + 128 * SW_STRIDE;      // 4*64 (sum)
    float* s_r2  = s_r1 + 256;                 // 4*64 (sumsq)
    float* s_mu  = s_r2 + 256;                 // 64
    float* s_rs  = s_mu + 64;                  // 64
    float* s_sq  = s_rs + 64;                  // 128

    int b = blockIdx.y;
    int p0 = blockIdx.x * PIX_TILE;
    int t = threadIdx.x;

    // load conv tile [128 ch][64 pix] (float4, coalesced)
    const float* cp = g_conv + (size_t)b * Cn * HW + p0;
    #pragma unroll
    for (int i = 0; i < 8; i++) {
        int idx = t + i * 256;                 // float4 index over 2048
        int c = idx >> 4;
        int p4 = (idx & 15) * 4;
        float4 v = *reinterpret_cast<const float4*>(&cp[(size_t)c * HW + p4]);
        *reinterpret_cast<float4*>(&s_ln[c * PIX_TILE + p4]) = v;
    }
    __syncthreads();

    // channel LN: per-pixel mean/var over 128 channels (4 partial quarters)
    {
        int q = t >> 6, p = t & 63;
        float s = 0.f, s2 = 0.f;
        for (int c = q * 32; c < q * 32 + 32; c++) {
            float v = s_ln[c * PIX_TILE + p];
            s += v; s2 += v * v;
        }
        s_r1[q * 64 + p] = s;
        s_r2[q * 64 + p] = s2;
    }
    __syncthreads();
    if (t < 64) {
        float s  = s_r1[t] + s_r1[64 + t] + s_r1[128 + t] + s_r1[192 + t];
        float s2 = s_r2[t] + s_r2[64 + t] + s_r2[128 + t] + s_r2[192 + t];
        float mu = s * (1.f / 128.f);
        float var = s2 * (1.f / 128.f) - mu * mu;
        s_mu[t] = mu;
        s_rs[t] = rsqrtf(var + EPSV);
    }
    __syncthreads();
    // normalize + ln2 affine, in place
    #pragma unroll
    for (int i = 0; i < 8; i++) {
        int idx = t + i * 256;
        int c = idx >> 4;
        int p4 = (idx & 15) * 4;
        float4 v = *reinterpret_cast<float4*>(&s_ln[c * PIX_TILE + p4]);
        float w = ln2w[c], bb = ln2b[c];
        float4 mu = *reinterpret_cast<float4*>(&s_mu[p4]);
        float4 rs = *reinterpret_cast<float4*>(&s_rs[p4]);
        v.x = (v.x - mu.x) * rs.x * w + bb;
        v.y = (v.y - mu.y) * rs.y * w + bb;
        v.z = (v.z - mu.z) * rs.z * w + bb;
        v.w = (v.w - mu.w) * rs.w * w + bb;
        *reinterpret_cast<float4*>(&s_ln[c * PIX_TILE + p4]) = v;
    }

    int pg = t & 15;          // pixel group: 4 pixels
    int og = t >> 4;          // oc group: 8 output channels
    int p4 = pg * 4;
    float* go = g_gelu + (size_t)b * CEn * HW + p0;

    for (int ot = 0; ot < 4; ot++) {
        int ocbase = ot * 128;
        __syncthreads();     // prev tile consumers done (and first-iter: LN writes visible)
        // load W_e tile [128 oc][128 k], natural layout, padded stride
        #pragma unroll
        for (int i = 0; i < 16; i++) {
            int idx = t + i * 256;             // float4 index over 4096
            int oc = idx >> 5;
            int k4 = (idx & 31) * 4;
            float4 v = *reinterpret_cast<const float4*>(&w_expand[(ocbase + oc) * Cn + k4]);
            *reinterpret_cast<float4*>(&s_w[oc * SW_STRIDE + k4]) = v;
        }
        if (t < 128) s_sq[t] = 0.f;
        __syncthreads();

        float acc[8][4];
        #pragma unroll
        for (int o = 0; o < 8; o++)
            #pragma unroll
            for (int p = 0; p < 4; p++) acc[o][p] = 0.f;

        #pragma unroll 2
        for (int k = 0; k < Cn; k += 4) {
            float4 b0 = *reinterpret_cast<const float4*>(&s_ln[(k + 0) * PIX_TILE + p4]);
            float4 b1 = *reinterpret_cast<const float4*>(&s_ln[(k + 1) * PIX_TILE + p4]);
            float4 b2 = *reinterpret_cast<const float4*>(&s_ln[(k + 2) * PIX_TILE + p4]);
            float4 b3 = *reinterpret_cast<const float4*>(&s_ln[(k + 3) * PIX_TILE + p4]);
            #pragma unroll
            for (int o = 0; o < 8; o++) {
                float4 a = *reinterpret_cast<const float4*>(&s_w[(og * 8 + o) * SW_STRIDE + k]);
                acc[o][0] += a.x * b0.x + a.y * b1.x + a.z * b2.x + a.w * b3.x;
                acc[o][1] += a.x * b0.y + a.y * b1.y + a.z * b2.y + a.w * b3.y;
                acc[o][2] += a.x * b0.z + a.y * b1.z + a.z * b2.z + a.w * b3.z;
                acc[o][3] += a.x * b0.w + a.y * b1.w + a.z * b2.w + a.w * b3.w;
            }
        }

        // gelu (exact) + store + GRN partial
        #pragma unroll
        for (int o = 0; o < 8; o++) {
            float sq = 0.f;
            #pragma unroll
            for (int p = 0; p < 4; p++) {
                float v = acc[o][p];
                float g = 0.5f * v * (1.f + erff(v * 0.7071067811865476f));
                acc[o][p] = g;
                sq += g * g;
            }
            int oc = ocbase + og * 8 + o;
            *reinterpret_cast<float4*>(&go[(size_t)oc * HW + p4]) =
                make_float4(acc[o][0], acc[o][1], acc[o][2], acc[o][3]);
            atomicAdd(&s_sq[og * 8 + o], sq);
        }
        __syncthreads();
        if (t < 128) atomicAdd(&g_sumsq[b * CEn + ocbase + t], s_sq[t]);
    }
}

// ---------------- k5: GRN finalize -> per-(b,ce) scale ----------------
__global__ void k_grn(const float* __restrict__ gamma) {
    int b = blockIdx.x, t = threadIdx.x;     // 512 threads
    float gx = sqrtf(g_sumsq[b * CEn + t]);
    __shared__ float sm[CEn];
    sm[t] = gx;
    __syncthreads();
    for (int o = 256; o > 0; o >>= 1) {
        if (t < o) sm[t] += sm[t + o];
        __syncthreads();
    }
    float mean = sm[0] * (1.f / (float)CEn);
    float nx = gx / (mean + EPSV);
    g_scale[b * CEn + t] = gamma[t] * nx + 1.f;
}

// ---------------- k6: shrink GEMM (scale+beta folded) + residual ----------------
// grid (49, 32), 256 threads, dynamic smem
#define WS_STRIDE 68
__global__ void k_shrink(const float* __restrict__ beta,
                         const float* __restrict__ w_shrink,
                         const float* __restrict__ x,
                         float* __restrict__ out) {
    extern __shared__ float sm[];
    float* s_ws = sm;                        // 128*68
    float* s_g  = s_ws + Cn * WS_STRIDE;     // 64*64

    int b = blockIdx.y;
    int p0 = blockIdx.x * PIX_TILE;
    int t = threadIdx.x;
    int pg = t & 15;
    int og = t >> 4;                         // 8 oc per thread
    int p4 = pg * 4;

    const float* gp = g_gelu + (size_t)b * CEn * HW + p0;

    float acc[8][4];
    #pragma unroll
    for (int o = 0; o < 8; o++)
        #pragma unroll
        for (int p = 0; p < 4; p++) acc[o][p] = 0.f;

    for (int kt = 0; kt < 8; kt++) {
        int k0 = kt * 64;
        __syncthreads();
        // w_shrink tile [128 oc][64 k]
        #pragma unroll
        for (int i = 0; i < 8; i++) {
            int idx = t + i * 256;           // float4 index over 2048
            int oc = idx >> 4;
            int k4 = (idx & 15) * 4;
            float4 v = *reinterpret_cast<const float4*>(&w_shrink[oc * CEn + k0 + k4]);
            *reinterpret_cast<float4*>(&s_ws[oc * WS_STRIDE + k4]) = v;
        }
        // gelu tile [64 k][64 p] with GRN scale & beta folded in
        #pragma unroll
        for (int i = 0; i < 4; i++) {
            int idx = t + i * 256;           // float4 index over 1024
            int k = idx >> 4;
            int pp = (idx & 15) * 4;
            float a  = g_scale[b * CEn + k0 + k];
            float bt = beta[k0 + k];
            float4 v = *reinterpret_cast<const float4*>(&gp[(size_t)(k0 + k) * HW + pp]);
            v.x = a * v.x + bt; v.y = a * v.y + bt; v.z = a * v.z + bt; v.w = a * v.w + bt;
            *reinterpret_cast<float4*>(&s_g[k * PIX_TILE + pp]) = v;
        }
        __syncthreads();

        #pragma unroll 2
        for (int k = 0; k < 64; k += 4) {
            float4 b0 = *reinterpret_cast<const float4*>(&s_g[(k + 0) * PIX_TILE + p4]);
            float4 b1 = *reinterpret_cast<const float4*>(&s_g[(k + 1) * PIX_TILE + p4]);
            float4 b2 = *reinterpret_cast<const float4*>(&s_g[(k + 2) * PIX_TILE + p4]);
            float4 b3 = *reinterpret_cast<const float4*>(&s_g[(k + 3) * PIX_TILE + p4]);
            #pragma unroll
            for (int o = 0; o < 8; o++) {
                float4 a = *reinterpret_cast<const float4*>(&s_ws[(og * 8 + o) * WS_STRIDE + k]);
                acc[o][0] += a.x * b0.x + a.y * b1.x + a.z * b2.x + a.w * b3.x;
                acc[o][1] += a.x * b0.y + a.y * b1.y + a.z * b2.y + a.w * b3.y;
                acc[o][2] += a.x * b0.z + a.y * b1.z + a.z * b2.z + a.w * b3.z;
                acc[o][3] += a.x * b0.w + a.y * b1.w + a.z * b2.w + a.w * b3.w;
            }
        }
    }

    // residual + store
    const float* xp = x + (size_t)b * Cn * HW + p0;
    float* op = out + (size_t)b * Cn * HW + p0;
    #pragma unroll
    for (int o = 0; o < 8; o++) {
        int oc = og * 8 + o;
        float4 xv = *reinterpret_cast<const float4*>(&xp[(size_t)oc * HW + p4]);
        float4 r = make_float4(acc[o][0] + xv.x, acc[o][1] + xv.y,
                               acc[o][2] + xv.z, acc[o][3] + xv.w);
        *reinterpret_cast<float4*>(&op[(size_t)oc * HW + p4]) = r;
    }
}

// ---------------- launch ----------------
extern "C" void kernel_launch(void* const* d_in, const int* in_sizes, int n_in,
                              void* d_out, int out_size) {
    const float* x        = (const float*)d_in[0];
    const float* w_fc1    = (const float*)d_in[1];
    const float* ln1_w    = (const float*)d_in[2];
    const float* ln1_b    = (const float*)d_in[3];
    const float* w_fc2    = (const float*)d_in[4];
    const float* ln2_w    = (const float*)d_in[5];
    const float* ln2_b    = (const float*)d_in[6];
    const float* w_expand = (const float*)d_in[7];
    const float* w_shrink = (const float*)d_in[8];
    const float* grn_g    = (const float*)d_in[9];
    const float* grn_b    = (const float*)d_in[10];
    float* out = (float*)d_out;

    // dynamic smem sizes
    const int SMEM_EXPAND = (Cn * PIX_TILE + 128 * SW_STRIDE + 256 + 256 + 64 + 64 + 128) * 4;
    const int SMEM_SHRINK = (Cn * WS_STRIDE + 64 * PIX_TILE) * 4;
    cudaFuncSetAttribute(k_expand, cudaFuncAttributeMaxDynamicSharedMemorySize, SMEM_EXPAND);
    cudaFuncSetAttribute(k_shrink, cudaFuncAttributeMaxDynamicSharedMemorySize, SMEM_SHRINK);

    k_zero<<<Bn, CEn>>>();
    k_pool<<<Bn * Cn, 256>>>(x);
    k_fc<<<Bn, 128>>>(w_fc1, ln1_w, ln1_b, w_fc2);
    k_conv<<<Bn * Cn, 256>>>(x);
    k_expand<<<dim3(NPT, Bn), 256, SMEM_EXPAND>>>(ln2_w, ln2_b, w_expand);
    k_grn<<<Bn, CEn>>>(grn_g);
    k_shrink<<<dim3(NPT, Bn), 256, SMEM_SHRINK>>>(grn_b, w_shrink, x, out);
}

// round 2
// speedup vs baseline: 1.6028x; 1.6028x over previous
#include <cuda_runtime.h>
#include <cstdint>
#include <math.h>

// Problem constants
#define Bn 32
#define Cn 128
#define Hn 56
#define Wn 56
#define Kn 5
#define CRn 32
#define CEn 512
#define HW 3136          // 56*56
#define PIX_TILE 64      // 3136 = 49*64
#define NPT 49           // pixel tiles per image
#define EPSV 1e-6f

// ---------------- scratch (device globals; no runtime allocation) ----------------
__device__ float g_pooled[Bn * Cn];
__device__ float g_dyn[Bn * Cn * 25];
__device__ float g_conv[(size_t)Bn * Cn * HW];            // 51.4 MB
__device__ float g_gelu[(size_t)Bn * CEn * HW];           // 205.5 MB
__device__ float g_sumsq[Bn * CEn];
__device__ float g_scale[Bn * CEn];

// ---------------- k0: zero GRN accumulator ----------------
__global__ void k_zero() {
    g_sumsq[blockIdx.x * CEn + threadIdx.x] = 0.f;
}

// ---------------- k1: global average pool ----------------
__global__ void k_pool(const float* __restrict__ x) {
    int bc = blockIdx.x;
    const float* p = x + (size_t)bc * HW;
    float s = 0.f;
    for (int i = threadIdx.x; i < HW / 4; i += 256) {
        float4 v = reinterpret_cast<const float4*>(p)[i];
        s += v.x + v.y + v.z + v.w;
    }
    __shared__ float sm[256];
    sm[threadIdx.x] = s;
    __syncthreads();
    for (int o = 128; o > 0; o >>= 1) {
        if (threadIdx.x < o) sm[threadIdx.x] += sm[threadIdx.x + o];
        __syncthreads();
    }
    if (threadIdx.x == 0) g_pooled[bc] = sm[0] * (1.f / (float)HW);
}

// ---------------- k2: fc1 -> LN1 -> fc2 (dyn kernels) ----------------
__global__ void k_fc(const float* __restrict__ w_fc1,
                     const float* __restrict__ ln1w, const float* __restrict__ ln1b,
                     const float* __restrict__ w_fc2) {
    int b = blockIdx.x;
    int t = threadIdx.x;              // 128 threads
    __shared__ float sp[Cn];
    __shared__ float sh[CRn];
    sp[t] = g_pooled[b * Cn + t];
    __syncthreads();
    if (t < 32) {
        const float* wr = w_fc1 + t * Cn;
        float a = 0.f;
        #pragma unroll
        for (int i = 0; i < Cn; i++) a += wr[i] * sp[i];
        float u = a;
        #pragma unroll
        for (int o = 16; o > 0; o >>= 1) u += __shfl_xor_sync(0xffffffffu, u, o);
        u *= (1.f / 32.f);
        float d = a - u;
        float v = d * d;
        #pragma unroll
        for (int o = 16; o > 0; o >>= 1) v += __shfl_xor_sync(0xffffffffu, v, o);
        v *= (1.f / 32.f);
        sh[t] = d * rsqrtf(v + EPSV) * ln1w[t] + ln1b[t];
    }
    __syncthreads();
    for (int i = t; i < Cn * 25; i += 128) {
        const float* wr = w_fc2 + i * CRn;
        float a = 0.f;
        #pragma unroll
        for (int j = 0; j < CRn; j++) a += wr[j] * sh[j];
        g_dyn[b * Cn * 25 + i] = a;
    }
}

// ---------------- k3: dynamic depthwise 5x5 conv ----------------
__global__ void k_conv(const float* __restrict__ x) {
    int bc = blockIdx.x;
    __shared__ float tile[60 * 60];
    const float* xp = x + (size_t)bc * HW;
    for (int i = threadIdx.x; i < 3600; i += 256) {
        int r = i / 60, cc = i % 60;
        int h = r - 2, w = cc - 2;
        tile[i] = (h >= 0 && h < Hn && w >= 0 && w < Wn) ? xp[h * Wn + w] : 0.f;
    }
    float kk[25];
    const float* dp = g_dyn + bc * 25;
    #pragma unroll
    for (int i = 0; i < 25; i++) kk[i] = dp[i];
    __syncthreads();
    float* op = g_conv + (size_t)bc * HW;
    for (int p = threadIdx.x; p < HW; p += 256) {
        int h = p / Wn, w = p % Wn;
        float a = 0.f;
        #pragma unroll
        for (int i = 0; i < 5; i++)
            #pragma unroll
            for (int j = 0; j < 5; j++)
                a += kk[i * 5 + j] * tile[(h + i) * 60 + (w + j)];
        op[p] = a;
    }
}

// ---------------- k4: channel-LN + expand GEMM + gelu + GRN partial sums ----------------
// grid (49, 32), 256 threads, dynamic smem
#define SW_STRIDE 132
__global__ void k_expand(const float* __restrict__ ln2w, const float* __restrict__ ln2b,
                         const float* __restrict__ w_expand) {
    extern __shared__ float sm[];
    float* s_ln  = sm;                         // 128*64
    float* s_w   = s_ln + Cn * PIX_TILE;       // 128*132
    float* s_r1  = s_w + 128 * SW_STRIDE;      // 4*64 (sum)
    float* s_r2  = s_r1 + 256;                 // 4*64 (sumsq)
    float* s_mu  = s_r2 + 256;                 // 64
    float* s_rs  = s_mu + 64;                  // 64
    float* s_sq  = s_rs + 64;                  // 128

    int b = blockIdx.y;
    int p0 = blockIdx.x * PIX_TILE;
    int t = threadIdx.x;

    // load conv tile [128 ch][64 pix] (float4, coalesced)
    const float* cp = g_conv + (size_t)b * Cn * HW + p0;
    #pragma unroll
    for (int i = 0; i < 8; i++) {
        int idx = t + i * 256;                 // float4 index over 2048
        int c = idx >> 4;
        int p4 = (idx & 15) * 4;
        float4 v = *reinterpret_cast<const float4*>(&cp[(size_t)c * HW + p4]);
        *reinterpret_cast<float4*>(&s_ln[c * PIX_TILE + p4]) = v;
    }
    __syncthreads();

    // channel LN: per-pixel mean/var over 128 channels (4 partial quarters)
    {
        int q = t >> 6, p = t & 63;
        float s = 0.f, s2 = 0.f;
        for (int c = q * 32; c < q * 32 + 32; c++) {
            float v = s_ln[c * PIX_TILE + p];
            s += v; s2 += v * v;
        }
        s_r1[q * 64 + p] = s;
        s_r2[q * 64 + p] = s2;
    }
    __syncthreads();
    if (t < 64) {
        float s  = s_r1[t] + s_r1[64 + t] + s_r1[128 + t] + s_r1[192 + t];
        float s2 = s_r2[t] + s_r2[64 + t] + s_r2[128 + t] + s_r2[192 + t];
        float mu = s * (1.f / 128.f);
        float var = s2 * (1.f / 128.f) - mu * mu;
        s_mu[t] = mu;
        s_rs[t] = rsqrtf(var + EPSV);
    }
    __syncthreads();
    // normalize + ln2 affine, in place
    #pragma unroll
    for (int i = 0; i < 8; i++) {
        int idx = t + i * 256;
        int c = idx >> 4;
        int p4 = (idx & 15) * 4;
        float4 v = *reinterpret_cast<float4*>(&s_ln[c * PIX_TILE + p4]);
        float w = ln2w[c], bb = ln2b[c];
        float4 mu = *reinterpret_cast<float4*>(&s_mu[p4]);
        float4 rs = *reinterpret_cast<float4*>(&s_rs[p4]);
        v.x = (v.x - mu.x) * rs.x * w + bb;
        v.y = (v.y - mu.y) * rs.y * w + bb;
        v.z = (v.z - mu.z) * rs.z * w + bb;
        v.w = (v.w - mu.w) * rs.w * w + bb;
        *reinterpret_cast<float4*>(&s_ln[c * PIX_TILE + p4]) = v;
    }

    int pg = t & 15;          // pixel group: 4 pixels
    int og = t >> 4;          // oc group: 8 output channels
    int p4 = pg * 4;
    float* go = g_gelu + (size_t)b * CEn * HW + p0;

    for (int ot = 0; ot < 4; ot++) {
        int ocbase = ot * 128;
        __syncthreads();     // prev tile consumers done (and first-iter: LN writes visible)
        // load W_e tile [128 oc][128 k], natural layout, padded stride
        #pragma unroll
        for (int i = 0; i < 16; i++) {
            int idx = t + i * 256;             // float4 index over 4096
            int oc = idx >> 5;
            int k4 = (idx & 31) * 4;
            float4 v = *reinterpret_cast<const float4*>(&w_expand[(ocbase + oc) * Cn + k4]);
            *reinterpret_cast<float4*>(&s_w[oc * SW_STRIDE + k4]) = v;
        }
        if (t < 128) s_sq[t] = 0.f;
        __syncthreads();

        float acc[8][4];
        #pragma unroll
        for (int o = 0; o < 8; o++)
            #pragma unroll
            for (int p = 0; p < 4; p++) acc[o][p] = 0.f;

        #pragma unroll 2
        for (int k = 0; k < Cn; k += 4) {
            float4 b0 = *reinterpret_cast<const float4*>(&s_ln[(k + 0) * PIX_TILE + p4]);
            float4 b1 = *reinterpret_cast<const float4*>(&s_ln[(k + 1) * PIX_TILE + p4]);
            float4 b2 = *reinterpret_cast<const float4*>(&s_ln[(k + 2) * PIX_TILE + p4]);
            float4 b3 = *reinterpret_cast<const float4*>(&s_ln[(k + 3) * PIX_TILE + p4]);
            #pragma unroll
            for (int o = 0; o < 8; o++) {
                float4 a = *reinterpret_cast<const float4*>(&s_w[(og * 8 + o) * SW_STRIDE + k]);
                acc[o][0] += a.x * b0.x + a.y * b1.x + a.z * b2.x + a.w * b3.x;
                acc[o][1] += a.x * b0.y + a.y * b1.y + a.z * b2.y + a.w * b3.y;
                acc[o][2] += a.x * b0.z + a.y * b1.z + a.z * b2.z + a.w * b3.z;
                acc[o][3] += a.x * b0.w + a.y * b1.w + a.z * b2.w + a.w * b3.w;
            }
        }

        // gelu (exact) + store + GRN partial
        #pragma unroll
        for (int o = 0; o < 8; o++) {
            float sq = 0.f;
            #pragma unroll
            for (int p = 0; p < 4; p++) {
                float v = acc[o][p];
                float g = 0.5f * v * (1.f + erff(v * 0.7071067811865476f));
                acc[o][p] = g;
                sq += g * g;
            }
            int oc = ocbase + og * 8 + o;
            *reinterpret_cast<float4*>(&go[(size_t)oc * HW + p4]) =
                make_float4(acc[o][0], acc[o][1], acc[o][2], acc[o][3]);
            atomicAdd(&s_sq[og * 8 + o], sq);
        }
        __syncthreads();
        if (t < 128) atomicAdd(&g_sumsq[b * CEn + ocbase + t], s_sq[t]);
    }
}

// ---------------- k5: GRN finalize -> per-(b,ce) scale ----------------
__global__ void k_grn(const float* __restrict__ gamma) {
    int b = blockIdx.x, t = threadIdx.x;     // 512 threads
    float gx = sqrtf(g_sumsq[b * CEn + t]);
    __shared__ float sm[CEn];
    sm[t] = gx;
    __syncthreads();
    for (int o = 256; o > 0; o >>= 1) {
        if (t < o) sm[t] += sm[t + o];
        __syncthreads();
    }
    float mean = sm[0] * (1.f / (float)CEn);
    float nx = gx / (mean + EPSV);
    g_scale[b * CEn + t] = gamma[t] * nx + 1.f;
}

// ---------------- k6: shrink GEMM (scale+beta folded) + residual ----------------
// grid (49, 32), 256 threads, dynamic smem
#define WS_STRIDE 68
__global__ void k_shrink(const float* __restrict__ beta,
                         const float* __restrict__ w_shrink,
                         const float* __restrict__ x,
                         float* __restrict__ out) {
    extern __shared__ float sm[];
    float* s_ws = sm;                        // 128*68
    float* s_g  = s_ws + Cn * WS_STRIDE;     // 64*64

    int b = blockIdx.y;
    int p0 = blockIdx.x * PIX_TILE;
    int t = threadIdx.x;
    int pg = t & 15;
    int og = t >> 4;                         // 8 oc per thread
    int p4 = pg * 4;

    const float* gp = g_gelu + (size_t)b * CEn * HW + p0;

    float acc[8][4];
    #pragma unroll
    for (int o = 0; o < 8; o++)
        #pragma unroll
        for (int p = 0; p < 4; p++) acc[o][p] = 0.f;

    for (int kt = 0; kt < 8; kt++) {
        int k0 = kt * 64;
        __syncthreads();
        // w_shrink tile [128 oc][64 k]
        #pragma unroll
        for (int i = 0; i < 8; i++) {
            int idx = t + i * 256;           // float4 index over 2048
            int oc = idx >> 4;
            int k4 = (idx & 15) * 4;
            float4 v = *reinterpret_cast<const float4*>(&w_shrink[oc * CEn + k0 + k4]);
            *reinterpret_cast<float4*>(&s_ws[oc * WS_STRIDE + k4]) = v;
        }
        // gelu tile [64 k][64 p] with GRN scale & beta folded in
        #pragma unroll
        for (int i = 0; i < 4; i++) {
            int idx = t + i * 256;           // float4 index over 1024
            int k = idx >> 4;
            int pp = (idx & 15) * 4;
            float a  = g_scale[b * CEn + k0 + k];
            float bt = beta[k0 + k];
            float4 v = *reinterpret_cast<const float4*>(&gp[(size_t)(k0 + k) * HW + pp]);
            v.x = a * v.x + bt; v.y = a * v.y + bt; v.z = a * v.z + bt; v.w = a * v.w + bt;
            *reinterpret_cast<float4*>(&s_g[k * PIX_TILE + pp]) = v;
        }
        __syncthreads();

        #pragma unroll 2
        for (int k = 0; k < 64; k += 4) {
            float4 b0 = *reinterpret_cast<const float4*>(&s_g[(k + 0) * PIX_TILE + p4]);
            float4 b1 = *reinterpret_cast<const float4*>(&s_g[(k + 1) * PIX_TILE + p4]);
            float4 b2 = *reinterpret_cast<const float4*>(&s_g[(k + 2) * PIX_TILE + p4]);
            float4 b3 = *reinterpret_cast<const float4*>(&s_g[(k + 3) * PIX_TILE + p4]);
            #pragma unroll
            for (int o = 0; o < 8; o++) {
                float4 a = *reinterpret_cast<const float4*>(&s_ws[(og * 8 + o) * WS_STRIDE + k]);
                acc[o][0] += a.x * b0.x + a.y * b1.x + a.z * b2.x + a.w * b3.x;
                acc[o][1] += a.x * b0.y + a.y * b1.y + a.z * b2.y + a.w * b3.y;
                acc[o][2] += a.x * b0.z + a.y * b1.z + a.z * b2.z + a.w * b3.z;
                acc[o][3] += a.x * b0.w + a.y * b1.w + a.z * b2.w + a.w * b3.w;
            }
        }
    }

    // residual + store
    const float* xp = x + (size_t)b * Cn * HW + p0;
    float* op = out + (size_t)b * Cn * HW + p0;
    #pragma unroll
    for (int o = 0; o < 8; o++) {
        int oc = og * 8 + o;
        float4 xv = *reinterpret_cast<const float4*>(&xp[(size_t)oc * HW + p4]);
        float4 r = make_float4(acc[o][0] + xv.x, acc[o][1] + xv.y,
                               acc[o][2] + xv.z, acc[o][3] + xv.w);
        *reinterpret_cast<float4*>(&op[(size_t)oc * HW + p4]) = r;
    }
}

// ---------------- launch ----------------
extern "C" void kernel_launch(void* const* d_in, const int* in_sizes, int n_in,
                              void* d_out, int out_size) {
    const float* x        = (const float*)d_in[0];
    const float* w_fc1    = (const float*)d_in[1];
    const float* ln1_w    = (const float*)d_in[2];
    const float* ln1_b    = (const float*)d_in[3];
    const float* w_fc2    = (const float*)d_in[4];
    const float* ln2_w    = (const float*)d_in[5];
    const float* ln2_b    = (const float*)d_in[6];
    const float* w_expand = (const float*)d_in[7];
    const float* w_shrink = (const float*)d_in[8];
    const float* grn_g    = (const float*)d_in[9];
    const float* grn_b    = (const float*)d_in[10];
    float* out = (float*)d_out;

    // dynamic smem sizes
    const int SMEM_EXPAND = (Cn * PIX_TILE + 128 * SW_STRIDE + 256 + 256 + 64 + 64 + 128) * 4;
    const int SMEM_SHRINK = (Cn * WS_STRIDE + 64 * PIX_TILE) * 4;
    cudaFuncSetAttribute(k_expand, cudaFuncAttributeMaxDynamicSharedMemorySize, SMEM_EXPAND);
    cudaFuncSetAttribute(k_shrink, cudaFuncAttributeMaxDynamicSharedMemorySize, SMEM_SHRINK);

    k_zero<<<Bn, CEn>>>();
    k_pool<<<Bn * Cn, 256>>>(x);
    k_fc<<<Bn, 128>>>(w_fc1, ln1_w, ln1_b, w_fc2);
    k_conv<<<Bn * Cn, 256>>>(x);
    k_expand<<<dim3(NPT, Bn), 256, SMEM_EXPAND>>>(ln2_w, ln2_b, w_expand);
    k_grn<<<Bn, CEn>>>(grn_g);
    k_shrink<<<dim3(NPT, Bn), 256, SMEM_SHRINK>>>(grn_b, w_shrink, x, out);
}

// round 4
// speedup vs baseline: 3.1165x; 1.9444x over previous
#include <cuda_runtime.h>
#include <cuda_bf16.h>
#include <cstdint>
#include <math.h>

#define Bn 32
#define Cn 128
#define Hn 56
#define Wn 56
#define HW 3136
#define CEn 512
#define EPSV 1e-6f

__device__ float g_pooled[Bn * Cn];
__device__ float g_dyn[Bn * Cn * 25];
__device__ float g_conv[(size_t)Bn * Cn * HW];
__device__ float g_gelu[(size_t)Bn * HW * CEn];   // [b][p][ce]
__device__ float g_sumsq[Bn * CEn];
__device__ float g_scale[Bn * CEn];
__device__ uint32_t g_wea[65536];   // expand W bf16x2: hi plane [512][64], lo at +32768
__device__ uint32_t g_wsa[65536];   // shrink W bf16x2: hi plane [128][256], lo at +32768

// ---------- helpers ----------
__device__ __forceinline__ uint32_t smem_u32(const void* p) {
    uint32_t a;
    asm("{ .reg .u64 t; cvta.to.shared.u64 t, %1; cvt.u32.u64 %0, t; }" : "=r"(a) : "l"(p));
    return a;
}
__device__ __forceinline__ void ldm4(uint32_t* r, uint32_t a) {
    asm volatile("ldmatrix.sync.aligned.m8n8.x4.shared.b16 {%0,%1,%2,%3}, [%4];"
        : "=r"(r[0]), "=r"(r[1]), "=r"(r[2]), "=r"(r[3]) : "r"(a));
}
__device__ __forceinline__ void mma_bf16(float* c, const uint32_t* a, const uint32_t* b) {
    asm volatile("mma.sync.aligned.m16n8k16.row.col.f32.bf16.bf16.f32 "
        "{%0,%1,%2,%3},{%4,%5,%6,%7},{%8,%9},{%0,%1,%2,%3};"
        : "+f"(c[0]), "+f"(c[1]), "+f"(c[2]), "+f"(c[3])
        : "r"(a[0]), "r"(a[1]), "r"(a[2]), "r"(a[3]), "r"(b[0]), "r"(b[1]));
}
__device__ __forceinline__ void split_pk(float a, float b, uint32_t& h, uint32_t& l) {
    __nv_bfloat16 ah = __float2bfloat16_rn(a), bh = __float2bfloat16_rn(b);
    __nv_bfloat16 al = __float2bfloat16_rn(a - __bfloat162float(ah));
    __nv_bfloat16 bl = __float2bfloat16_rn(b - __bfloat162float(bh));
    h = (uint32_t)__bfloat16_as_ushort(ah) | ((uint32_t)__bfloat16_as_ushort(bh) << 16);
    l = (uint32_t)__bfloat16_as_ushort(al) | ((uint32_t)__bfloat16_as_ushort(bl) << 16);
}
__device__ __forceinline__ float gelu_f(float v) { return 0.5f * v * (1.f + erff(v * 0.7071067811865476f)); }

// ---------- weight preconversion: split f32 -> bf16 hi/lo planes ----------
__global__ void k_wprep(const float* __restrict__ src, int which, int shift) {
    int g = blockIdx.x * 256 + threadIdx.x;         // 32768
    int kp = g & ((1 << shift) - 1), row = g >> shift;
    const float* s = src + (size_t)row * (2 << shift) + 2 * kp;
    uint32_t h, l;
    split_pk(s[0], s[1], h, l);
    uint32_t* dst = which ? g_wsa : g_wea;
    dst[(row << shift) + kp] = h;
    dst[32768 + (row << shift) + kp] = l;
}

// ---------- small kernels ----------
__global__ void k_zero() { g_sumsq[blockIdx.x * CEn + threadIdx.x] = 0.f; }

__global__ void k_pool(const float* __restrict__ x) {
    int bc = blockIdx.x;
    const float* p = x + (size_t)bc * HW;
    float s = 0.f;
    for (int i = threadIdx.x; i < HW / 4; i += 256) {
        float4 v = reinterpret_cast<const float4*>(p)[i];
        s += v.x + v.y + v.z + v.w;
    }
    __shared__ float sm[256];
    sm[threadIdx.x] = s;
    __syncthreads();
    for (int o = 128; o > 0; o >>= 1) {
        if (threadIdx.x < o) sm[threadIdx.x] += sm[threadIdx.x + o];
        __syncthreads();
    }
    if (threadIdx.x == 0) g_pooled[bc] = sm[0] * (1.f / (float)HW);
}

__global__ void k_fc(const float* __restrict__ w_fc1, const float* __restrict__ ln1w,
                     const float* __restrict__ ln1b, const float* __restrict__ w_fc2) {
    int b = blockIdx.x, t = threadIdx.x;
    __shared__ float sp[Cn];
    __shared__ float sh[32];
    sp[t] = g_pooled[b * Cn + t];
    __syncthreads();
    if (t < 32) {
        const float* wr = w_fc1 + t * Cn;
        float a = 0.f;
        #pragma unroll
        for (int i = 0; i < Cn; i++) a += wr[i] * sp[i];
        float u = a;
        #pragma unroll
        for (int o = 16; o > 0; o >>= 1) u += __shfl_xor_sync(~0u, u, o);
        u *= (1.f / 32.f);
        float d = a - u, v = d * d;
        #pragma unroll
        for (int o = 16; o > 0; o >>= 1) v += __shfl_xor_sync(~0u, v, o);
        v *= (1.f / 32.f);
        sh[t] = d * rsqrtf(v + EPSV) * ln1w[t] + ln1b[t];
    }
    __syncthreads();
    for (int i = t; i < Cn * 25; i += 128) {
        const float* wr = w_fc2 + i * 32;
        float a = 0.f;
        #pragma unroll
        for (int j = 0; j < 32; j++) a += wr[j] * sh[j];
        g_dyn[b * Cn * 25 + i] = a;
    }
}

__global__ void k_conv(const float* __restrict__ x) {
    int bc = blockIdx.x;
    __shared__ float tile[60 * 60];
    const float* xp = x + (size_t)bc * HW;
    for (int i = threadIdx.x; i < 3600; i += 256) {
        int r = i / 60, cc = i % 60, h = r - 2, w = cc - 2;
        tile[i] = (h >= 0 && h < Hn && w >= 0 && w < Wn) ? xp[h * Wn + w] : 0.f;
    }
    float kk[25];
    const float* dp = g_dyn + bc * 25;
    #pragma unroll
    for (int i = 0; i < 25; i++) kk[i] = dp[i];
    __syncthreads();
    float* op = g_conv + (size_t)bc * HW;
    for (int p = threadIdx.x; p < HW; p += 256) {
        int h = p / Wn, w = p % Wn;
        float a = 0.f;
        #pragma unroll
        for (int i = 0; i < 5; i++)
            #pragma unroll
            for (int j = 0; j < 5; j++)
                a += kk[i * 5 + j] * tile[(h + i) * 60 + (w + j)];
        op[p] = a;
    }
}

// ---------- expand: LN2 + mma.sync GEMM + gelu + GRN sumsq ----------
// smem: y_hi [112 rows p][128 c]bf16 stride 272B at 0 (30464); y_lo at 30464
//       A region at 61440: hi [128 oc][128 k] stride 272B (34816), lo at +34816
//       stage f32 (stride 117) and s_out f32 (stride 113) alias the A region
//       misc at 131072; total 134784
#define E_SMEM 134784
__global__ void __launch_bounds__(256, 1)
k_expand(const float* __restrict__ ln2w, const float* __restrict__ ln2b) {
    extern __shared__ char sb[];
    uint32_t sbu = smem_u32(sb);
    int t = threadIdx.x, wid = t >> 5, lane = t & 31;
    int b = blockIdx.y, p0 = blockIdx.x * 112;
    float* stage = (float*)(sb + 61440);
    float* s_lnw = (float*)(sb + 131072);
    float* s_lnb = (float*)(sb + 131584);
    float* r1 = (float*)(sb + 132096);
    float* r2 = (float*)(sb + 132992);
    float* smu = (float*)(sb + 133888);
    float* srs = (float*)(sb + 134336);
    if (t < 128) { s_lnw[t] = ln2w[t]; s_lnb[t] = ln2b[t]; }
    const float* cp = g_conv + (size_t)b * Cn * HW + p0;
    #pragma unroll
    for (int i = 0; i < 14; i++) {
        int idx = t + i * 256, c = idx / 28, q = (idx % 28) * 4;
        float4 v = *(const float4*)&cp[(size_t)c * HW + q];
        float* d = &stage[c * 117 + q];
        d[0] = v.x; d[1] = v.y; d[2] = v.z; d[3] = v.w;
    }
    __syncthreads();
    if (t < 224) {
        int p = t % 112, h = t / 112;
        float s = 0.f, s2 = 0.f;
        for (int c = h * 64; c < h * 64 + 64; c++) {
            float v = stage[c * 117 + p];
            s += v; s2 += v * v;
        }
        r1[t] = s; r2[t] = s2;
    }
    __syncthreads();
    if (t < 112) {
        float s = r1[t] + r1[112 + t], s2 = r2[t] + r2[112 + t];
        float mu = s * (1.f / 128.f);
        smu[t] = mu;
        srs[t] = rsqrtf(s2 * (1.f / 128.f) - mu * mu + EPSV);
    }
    __syncthreads();
    // y = LN(conv)*w+b, transposed [p][c], bf16 hi/lo
    #pragma unroll
    for (int i = 0; i < 28; i++) {
        int idx = t + i * 256, p = idx >> 6, cp2 = idx & 63, c0 = cp2 * 2;
        float mu = smu[p], rs = srs[p];
        float v0 = (stage[c0 * 117 + p] - mu) * rs * s_lnw[c0] + s_lnb[c0];
        float v1 = (stage[(c0 + 1) * 117 + p] - mu) * rs * s_lnw[c0 + 1] + s_lnb[c0 + 1];
        uint32_t h, l;
        split_pk(v0, v1, h, l);
        *(uint32_t*)(sb + p * 272 + cp2 * 4) = h;
        *(uint32_t*)(sb + 30464 + p * 272 + cp2 * 4) = l;
    }
    __syncthreads();          // stage dead; y ready
    uint32_t aA = sbu + 61440 + (wid * 16 + (lane & 15)) * 272 + (lane >> 4) * 16;
    uint32_t aB = sbu + ((lane & 7) + ((lane >> 4) & 1) * 8) * 272 + ((lane >> 3) & 1) * 16;
    float* s_out = (float*)(sb + 61440);
    for (int m = 0; m < 4; m++) {
        // copy A chunk (bf16 hi/lo) into smem
        const uint4* s0 = (const uint4*)g_wea;
        #pragma unroll
        for (int i = 0; i < 16; i++) {
            int idx = t + i * 256;
            int pl = idx >> 11, r = (idx >> 4) & 127, q = idx & 15;
            uint4 v = s0[pl * 8192 + (m * 128 + r) * 16 + q];
            *(uint4*)(sb + 61440 + pl * 34816 + r * 272 + q * 16) = v;
        }
        __syncthreads();
        float acc[14][4];
        #pragma unroll
        for (int n = 0; n < 14; n++) { acc[n][0] = acc[n][1] = acc[n][2] = acc[n][3] = 0.f; }
        #pragma unroll
        for (int k = 0; k < 8; k++) {
            uint32_t ah[4], al[4];
            ldm4(ah, aA + k * 32);
            ldm4(al, aA + 34816 + k * 32);
            #pragma unroll
            for (int np = 0; np < 7; np++) {
                uint32_t bh[4], bl[4];
                uint32_t ba = aB + np * 4352 + k * 32;
                ldm4(bh, ba);
                ldm4(bl, ba + 30464);
                mma_bf16(acc[2 * np], ah, bh);
                mma_bf16(acc[2 * np], ah, bl);
                mma_bf16(acc[2 * np], al, bh);
                mma_bf16(acc[2 * np + 1], ah, bh + 2);
                mma_bf16(acc[2 * np + 1], ah, bl + 2);
                mma_bf16(acc[2 * np + 1], al, bh + 2);
            }
        }
        __syncthreads();      // done reading A; s_out aliases A region
        int r0 = wid * 16 + (lane >> 2), cbase = (lane & 3) * 2;
        #pragma unroll
        for (int n = 0; n < 14; n++) {
            int cc = n * 8 + cbase;
            s_out[r0 * 113 + cc] = acc[n][0];
            s_out[r0 * 113 + cc + 1] = acc[n][1];
            s_out[(r0 + 8) * 113 + cc] = acc[n][2];
            s_out[(r0 + 8) * 113 + cc + 1] = acc[n][3];
        }
        __syncthreads();
        int oc = t & 127, half = t >> 7;
        float ss = 0.f;
        float* go = g_gelu + ((size_t)b * HW + p0) * CEn + m * 128 + oc;
        #pragma unroll 4
        for (int j = 0; j < 56; j++) {
            int p = 2 * j + half;
            float g = gelu_f(s_out[oc * 113 + p]);
            ss += g * g;
            go[(size_t)p * CEn] = g;
        }
        atomicAdd(&g_sumsq[b * CEn + m * 128 + oc], ss);
        __syncthreads();
    }
}

__global__ void k_grn(const float* __restrict__ gamma) {
    int b = blockIdx.x, t = threadIdx.x;
    float gx = sqrtf(g_sumsq[b * CEn + t]);
    __shared__ float sm[CEn];
    sm[t] = gx;
    __syncthreads();
    for (int o = 256; o > 0; o >>= 1) {
        if (t < o) sm[t] += sm[t + o];
        __syncthreads();
    }
    g_scale[b * CEn + t] = gamma[t] * (gx / (sm[0] * (1.f / (float)CEn) + EPSV)) + 1.f;
}

// ---------- shrink: mma.sync GEMM (scale/beta folded) + residual ----------
// smem: z hi [64 p][128 ce] stride 272B at 0 (17408), lo at 17408
//       A at 34816: hi [128 oc][128 ce] (34816), lo at +34816 ; s_out f32 [128][68] aliases z
#define S_SMEM 104448
__global__ void __launch_bounds__(256, 2)
k_shrink(const float* __restrict__ beta, const float* __restrict__ x, float* __restrict__ out) {
    extern __shared__ char sb[];
    uint32_t sbu = smem_u32(sb);
    int t = threadIdx.x, wid = t >> 5, lane = t & 31;
    int b = blockIdx.y, p0 = blockIdx.x * 64;
    const float* gz = g_gelu + ((size_t)b * HW + p0) * CEn;
    float acc[8][4];
    #pragma unroll
    for (int n = 0; n < 8; n++) acc[n][0] = acc[n][1] = acc[n][2] = acc[n][3] = 0.f;
    uint32_t aA = sbu + 34816 + (wid * 16 + (lane & 15)) * 272 + (lane >> 4) * 16;
    uint32_t aB = sbu + ((lane & 7) + ((lane >> 4) & 1) * 8) * 272 + ((lane >> 3) & 1) * 16;
    for (int kt = 0; kt < 4; kt++) {
        __syncthreads();
        // A chunk
        const uint4* s0 = (const uint4*)g_wsa;
        #pragma unroll
        for (int i = 0; i < 16; i++) {
            int idx = t + i * 256;
            int pl = idx >> 11, r = (idx >> 4) & 127, q = idx & 15;
            uint4 v = s0[pl * 8192 + r * 64 + kt * 16 + q];
            *(uint4*)(sb + 34816 + pl * 34816 + r * 272 + q * 16) = v;
        }
        // z tile: a*gelu + beta, split bf16
        #pragma unroll
        for (int i = 0; i < 8; i++) {
            int idx = t + i * 256;
            int p = idx >> 5, q = idx & 31;
            int ce = kt * 128 + q * 4;
            float4 v = *(const float4*)&gz[(size_t)p * CEn + ce];
            float4 a = *(const float4*)&g_scale[b * CEn + ce];
            float4 bt = *(const float4*)&beta[ce];
            v.x = a.x * v.x + bt.x; v.y = a.y * v.y + bt.y;
            v.z = a.z * v.z + bt.z; v.w = a.w * v.w + bt.w;
            uint32_t h0, l0, h1, l1;
            split_pk(v.x, v.y, h0, l0);
            split_pk(v.z, v.w, h1, l1);
            *(uint2*)(sb + p * 272 + q * 8) = make_uint2(h0, h1);
            *(uint2*)(sb + 17408 + p * 272 + q * 8) = make_uint2(l0, l1);
        }
        __syncthreads();
        #pragma unroll
        for (int k = 0; k < 8; k++) {
            uint32_t ah[4], al[4];
            ldm4(ah, aA + k * 32);
            ldm4(al, aA + 34816 + k * 32);
            #pragma unroll
            for (int np = 0; np < 4; np++) {
                uint32_t bh[4], bl[4];
                uint32_t ba = aB + np * 4352 + k * 32;
                ldm4(bh, ba);
                ldm4(bl, ba + 17408);
                mma_bf16(acc[2 * np], ah, bh);
                mma_bf16(acc[2 * np], ah, bl);
                mma_bf16(acc[2 * np], al, bh);
                mma_bf16(acc[2 * np + 1], ah, bh + 2);
                mma_bf16(acc[2 * np + 1], ah, bl + 2);
                mma_bf16(acc[2 * np + 1], al, bh + 2);
            }
        }
    }
    __syncthreads();
    float* s_out = (float*)sb;   // [128][68]
    int r0 = wid * 16 + (lane >> 2), cbase = (lane & 3) * 2;
    #pragma unroll
    for (int n = 0; n < 8; n++) {
        int cc = n * 8 + cbase;
        s_out[r0 * 68 + cc] = acc[n][0];
        s_out[r0 * 68 + cc + 1] = acc[n][1];
        s_out[(r0 + 8) * 68 + cc] = acc[n][2];
        s_out[(r0 + 8) * 68 + cc + 1] = acc[n][3];
    }
    __syncthreads();
    const float* xp = x + (size_t)b * Cn * HW + p0;
    float* op = out + (size_t)b * Cn * HW + p0;
    #pragma unroll
    for (int i = 0; i < 8; i++) {
        int idx = t + i * 256, oc = idx >> 4, p4 = (idx & 15) * 4;
        float4 v = *(float4*)&s_out[oc * 68 + p4];
        float4 xv = *(const float4*)&xp[(size_t)oc * HW + p4];
        v.x += xv.x; v.y += xv.y; v.z += xv.z; v.w += xv.w;
        *(float4*)&op[(size_t)oc * HW + p4] = v;
    }
}

// ---------- launch ----------
extern "C" void kernel_launch(void* const* d_in, const int* in_sizes, int n_in,
                              void* d_out, int out_size) {
    const float* x        = (const float*)d_in[0];
    const float* w_fc1    = (const float*)d_in[1];
    const float* ln1_w    = (const float*)d_in[2];
    const float* ln1_b    = (const float*)d_in[3];
    const float* w_fc2    = (const float*)d_in[4];
    const float* ln2_w    = (const float*)d_in[5];
    const float* ln2_b    = (const float*)d_in[6];
    const float* w_expand = (const float*)d_in[7];
    const float* w_shrink = (const float*)d_in[8];
    const float* grn_g    = (const float*)d_in[9];
    const float* grn_b    = (const float*)d_in[10];
    float* out = (float*)d_out;

    cudaFuncSetAttribute(k_expand, cudaFuncAttributeMaxDynamicSharedMemorySize, E_SMEM);
    cudaFuncSetAttribute(k_shrink, cudaFuncAttributeMaxDynamicSharedMemorySize, S_SMEM);

    k_wprep<<<128, 256>>>(w_expand, 0, 6);
    k_wprep<<<128, 256>>>(w_shrink, 1, 8);
    k_zero<<<Bn, CEn>>>();
    k_pool<<<Bn * Cn, 256>>>(x);
    k_fc<<<Bn, 128>>>(w_fc1, ln1_w, ln1_b, w_fc2);
    k_conv<<<Bn * Cn, 256>>>(x);
    k_expand<<<dim3(28, Bn), 256, E_SMEM>>>(ln2_w, ln2_b);
    k_grn<<<Bn, CEn>>>(grn_g);
    k_shrink<<<dim3(49, Bn), 256, S_SMEM>>>(grn_b, x, out);
}

// round 5
// speedup vs baseline: 3.9951x; 1.2819x over previous
#include <cuda_runtime.h>
#include <cuda_fp16.h>
#include <cstdint>
#include <math.h>

#define Bn 32
#define Cn 128
#define Hn 56
#define Wn 56
#define HW 3136
#define CEn 512
#define EPSV 1e-6f

__device__ float g_pooled[Bn * Cn];
__device__ float g_dyn[Bn * Cn * 25];
__device__ float g_conv[(size_t)Bn * Cn * HW];
__device__ __half g_gelu[(size_t)Bn * HW * CEn];   // [b][p][ce] fp16
__device__ float g_sumsq[Bn * CEn];
__device__ float g_scale[Bn * CEn];
__device__ uint32_t g_wea[32768];   // expand W fp16x2 [512][64]
__device__ uint32_t g_wsa[32768];   // shrink W fp16x2 [128][256]

// ---------- helpers ----------
__device__ __forceinline__ uint32_t smem_u32(const void* p) {
    uint32_t a;
    asm("{ .reg .u64 t; cvta.to.shared.u64 t, %1; cvt.u32.u64 %0, t; }" : "=r"(a) : "l"(p));
    return a;
}
__device__ __forceinline__ void ldm4(uint32_t* r, uint32_t a) {
    asm volatile("ldmatrix.sync.aligned.m8n8.x4.shared.b16 {%0,%1,%2,%3}, [%4];"
        : "=r"(r[0]), "=r"(r[1]), "=r"(r[2]), "=r"(r[3]) : "r"(a));
}
__device__ __forceinline__ void mma_f16(float* c, const uint32_t* a, const uint32_t* b) {
    asm volatile("mma.sync.aligned.m16n8k16.row.col.f32.f16.f16.f32 "
        "{%0,%1,%2,%3},{%4,%5,%6,%7},{%8,%9},{%0,%1,%2,%3};"
        : "+f"(c[0]), "+f"(c[1]), "+f"(c[2]), "+f"(c[3])
        : "r"(a[0]), "r"(a[1]), "r"(a[2]), "r"(a[3]), "r"(b[0]), "r"(b[1]));
}
__device__ __forceinline__ uint32_t pkh2(float a, float b) {
    __half2 h = __floats2half2_rn(a, b);
    return *(uint32_t*)&h;
}
__device__ __forceinline__ float gelu_f(float v) { return 0.5f * v * (1.f + erff(v * 0.7071067811865476f)); }

// ---------- weight preconversion ----------
__global__ void k_wprep(const float* __restrict__ src, int which, int shift) {
    int g = blockIdx.x * 256 + threadIdx.x;         // 32768
    int kp = g & ((1 << shift) - 1), row = g >> shift;
    const float* s = src + (size_t)row * (2 << shift) + 2 * kp;
    uint32_t* dst = which ? g_wsa : g_wea;
    dst[(row << shift) + kp] = pkh2(s[0], s[1]);
}

// ---------- small kernels ----------
__global__ void k_zero() { g_sumsq[blockIdx.x * CEn + threadIdx.x] = 0.f; }

__global__ void k_pool(const float* __restrict__ x) {
    int bc = blockIdx.x;
    const float* p = x + (size_t)bc * HW;
    float s = 0.f;
    for (int i = threadIdx.x; i < HW / 4; i += 256) {
        float4 v = reinterpret_cast<const float4*>(p)[i];
        s += v.x + v.y + v.z + v.w;
    }
    __shared__ float sm[256];
    sm[threadIdx.x] = s;
    __syncthreads();
    for (int o = 128; o > 0; o >>= 1) {
        if (threadIdx.x < o) sm[threadIdx.x] += sm[threadIdx.x + o];
        __syncthreads();
    }
    if (threadIdx.x == 0) g_pooled[bc] = sm[0] * (1.f / (float)HW);
}

__global__ void k_fc(const float* __restrict__ w_fc1, const float* __restrict__ ln1w,
                     const float* __restrict__ ln1b, const float* __restrict__ w_fc2) {
    int b = blockIdx.x, t = threadIdx.x;
    __shared__ float sp[Cn];
    __shared__ float sh[32];
    sp[t] = g_pooled[b * Cn + t];
    __syncthreads();
    if (t < 32) {
        const float* wr = w_fc1 + t * Cn;
        float a = 0.f;
        #pragma unroll
        for (int i = 0; i < Cn; i++) a += wr[i] * sp[i];
        float u = a;
        #pragma unroll
        for (int o = 16; o > 0; o >>= 1) u += __shfl_xor_sync(~0u, u, o);
        u *= (1.f / 32.f);
        float d = a - u, v = d * d;
        #pragma unroll
        for (int o = 16; o > 0; o >>= 1) v += __shfl_xor_sync(~0u, v, o);
        v *= (1.f / 32.f);
        sh[t] = d * rsqrtf(v + EPSV) * ln1w[t] + ln1b[t];
    }
    __syncthreads();
    for (int i = t; i < Cn * 25; i += 128) {
        const float* wr = w_fc2 + i * 32;
        float a = 0.f;
        #pragma unroll
        for (int j = 0; j < 32; j++) a += wr[j] * sh[j];
        g_dyn[b * Cn * 25 + i] = a;
    }
}

__global__ void k_conv(const float* __restrict__ x) {
    int bc = blockIdx.x;
    __shared__ float tile[60 * 60];
    const float* xp = x + (size_t)bc * HW;
    for (int i = threadIdx.x; i < 3600; i += 256) {
        int r = i / 60, cc = i % 60, h = r - 2, w = cc - 2;
        tile[i] = (h >= 0 && h < Hn && w >= 0 && w < Wn) ? xp[h * Wn + w] : 0.f;
    }
    float kk[25];
    const float* dp = g_dyn + bc * 25;
    #pragma unroll
    for (int i = 0; i < 25; i++) kk[i] = dp[i];
    __syncthreads();
    float* op = g_conv + (size_t)bc * HW;
    for (int q = threadIdx.x; q < 784; q += 256) {
        int h = q / 14, w0 = (q % 14) * 4;
        float a0 = 0.f, a1 = 0.f, a2 = 0.f, a3 = 0.f;
        #pragma unroll
        for (int i = 0; i < 5; i++) {
            const float* r = &tile[(h + i) * 60 + w0];
            float r0 = r[0], r1 = r[1], r2 = r[2], r3 = r[3];
            float r4 = r[4], r5 = r[5], r6 = r[6], r7 = r[7];
            float k0 = kk[i * 5], k1 = kk[i * 5 + 1], k2 = kk[i * 5 + 2];
            float k3 = kk[i * 5 + 3], k4 = kk[i * 5 + 4];
            a0 += k0 * r0 + k1 * r1 + k2 * r2 + k3 * r3 + k4 * r4;
            a1 += k0 * r1 + k1 * r2 + k2 * r3 + k3 * r4 + k4 * r5;
            a2 += k0 * r2 + k1 * r3 + k2 * r4 + k3 * r5 + k4 * r6;
            a3 += k0 * r3 + k1 * r4 + k2 * r5 + k3 * r6 + k4 * r7;
        }
        *reinterpret_cast<float4*>(&op[q * 4]) = make_float4(a0, a1, a2, a3);
    }
}

// ---------- expand: LN2 + fp16 mma GEMM + gelu + GRN sumsq ----------
// smem: y [112 px][128 c]fp16 stride 272 at 0 (30464)
//       A at 30720: [128 oc][128 k]fp16 stride 272 (34816) -> 65536
//       s_out f32 [128 oc][113 px] at 65536 (57856) -> 123392
//       stage f32 [128][117] aliases 30720..90624
//       misc at 123392 (3712)
#define E_SMEM 127104
__global__ void __launch_bounds__(256, 1)
k_expand(const float* __restrict__ ln2w, const float* __restrict__ ln2b) {
    extern __shared__ char sb[];
    uint32_t sbu = smem_u32(sb);
    int t = threadIdx.x, wid = t >> 5, lane = t & 31;
    int b = blockIdx.y, p0 = blockIdx.x * 112;
    float* stage = (float*)(sb + 30720);
    float* s_lnw = (float*)(sb + 123392);
    float* s_lnb = (float*)(sb + 123904);
    float* r1 = (float*)(sb + 124416);
    float* r2 = (float*)(sb + 125312);
    float* smu = (float*)(sb + 126208);
    float* srs = (float*)(sb + 126656);
    if (t < 128) { s_lnw[t] = ln2w[t]; s_lnb[t] = ln2b[t]; }
    const float* cp = g_conv + (size_t)b * Cn * HW + p0;
    #pragma unroll
    for (int i = 0; i < 14; i++) {
        int idx = t + i * 256, c = idx / 28, q = (idx % 28) * 4;
        float4 v = *(const float4*)&cp[(size_t)c * HW + q];
        float* d = &stage[c * 117 + q];
        d[0] = v.x; d[1] = v.y; d[2] = v.z; d[3] = v.w;
    }
    __syncthreads();
    if (t < 224) {
        int p = t % 112, h = t / 112;
        float s = 0.f, s2 = 0.f;
        for (int c = h * 64; c < h * 64 + 64; c++) {
            float v = stage[c * 117 + p];
            s += v; s2 += v * v;
        }
        r1[t] = s; r2[t] = s2;
    }
    __syncthreads();
    if (t < 112) {
        float s = r1[t] + r1[112 + t], s2 = r2[t] + r2[112 + t];
        float mu = s * (1.f / 128.f);
        smu[t] = mu;
        srs[t] = rsqrtf(s2 * (1.f / 128.f) - mu * mu + EPSV);
    }
    __syncthreads();
    // y = LN(conv)*w+b, transposed [px][c], fp16
    #pragma unroll
    for (int i = 0; i < 28; i++) {
        int idx = t + i * 256, p = idx >> 6, cp2 = idx & 63, c0 = cp2 * 2;
        float mu = smu[p], rs = srs[p];
        float v0 = (stage[c0 * 117 + p] - mu) * rs * s_lnw[c0] + s_lnb[c0];
        float v1 = (stage[(c0 + 1) * 117 + p] - mu) * rs * s_lnw[c0 + 1] + s_lnb[c0 + 1];
        *(uint32_t*)(sb + p * 272 + cp2 * 4) = pkh2(v0, v1);
    }
    __syncthreads();          // stage dead; y ready
    uint32_t aA = sbu + 30720 + (wid * 16 + (lane & 15)) * 272 + (lane >> 4) * 16;
    uint32_t aB = sbu + ((lane & 7) + ((lane >> 4) & 1) * 8) * 272 + ((lane >> 3) & 1) * 16;
    float* s_out = (float*)(sb + 65536);
    for (int m = 0; m < 4; m++) {
        // copy A chunk fp16 into smem
        const uint4* s0 = (const uint4*)g_wea;
        #pragma unroll
        for (int i = 0; i < 8; i++) {
            int idx = t + i * 256;
            int r = idx >> 4, q = idx & 15;
            uint4 v = s0[(m * 128 + r) * 16 + q];
            *(uint4*)(sb + 30720 + r * 272 + q * 16) = v;
        }
        __syncthreads();
        float acc[14][4];
        #pragma unroll
        for (int n = 0; n < 14; n++) { acc[n][0] = acc[n][1] = acc[n][2] = acc[n][3] = 0.f; }
        #pragma unroll
        for (int k = 0; k < 8; k++) {
            uint32_t ah[4];
            ldm4(ah, aA + k * 32);
            #pragma unroll
            for (int np = 0; np < 7; np++) {
                uint32_t bh[4];
                ldm4(bh, aB + np * 4352 + k * 32);
                mma_f16(acc[2 * np], ah, bh);
                mma_f16(acc[2 * np + 1], ah, bh + 2);
            }
        }
        __syncthreads();
        int r0 = wid * 16 + (lane >> 2), cbase = (lane & 3) * 2;
        #pragma unroll
        for (int n = 0; n < 14; n++) {
            int cc = n * 8 + cbase;
            s_out[r0 * 113 + cc] = acc[n][0];
            s_out[r0 * 113 + cc + 1] = acc[n][1];
            s_out[(r0 + 8) * 113 + cc] = acc[n][2];
            s_out[(r0 + 8) * 113 + cc + 1] = acc[n][3];
        }
        __syncthreads();
        // gelu + half2 store + GRN sumsq (64 oc-pairs x 4 px phases)
        int u = t & 63, phase = t >> 6, oc2 = 2 * u;
        float ss0 = 0.f, ss1 = 0.f;
        __half* go = g_gelu + ((size_t)b * HW + p0) * CEn + m * 128 + oc2;
        #pragma unroll 4
        for (int j = 0; j < 28; j++) {
            int p = phase + 4 * j;
            float f0 = gelu_f(s_out[oc2 * 113 + p]);
            float f1 = gelu_f(s_out[(oc2 + 1) * 113 + p]);
            ss0 += f0 * f0; ss1 += f1 * f1;
            *(uint32_t*)&go[(size_t)p * CEn] = pkh2(f0, f1);
        }
        atomicAdd(&g_sumsq[b * CEn + m * 128 + oc2], ss0);
        atomicAdd(&g_sumsq[b * CEn + m * 128 + oc2 + 1], ss1);
        __syncthreads();
    }
}

__global__ void k_grn(const float* __restrict__ gamma) {
    int b = blockIdx.x, t = threadIdx.x;
    float gx = sqrtf(g_sumsq[b * CEn + t]);
    __shared__ float sm[CEn];
    sm[t] = gx;
    __syncthreads();
    for (int o = 256; o > 0; o >>= 1) {
        if (t < o) sm[t] += sm[t + o];
        __syncthreads();
    }
    g_scale[b * CEn + t] = gamma[t] * (gx / (sm[0] * (1.f / (float)CEn) + EPSV)) + 1.f;
}

// ---------- shrink: fp16 mma GEMM (scale/beta folded) + residual ----------
// smem: z [64 px][128 ce]fp16 stride 272 at 0 (17408)
//       A [128 oc][128 ce]fp16 stride 272 at 17408 (34816) -> 52224
//       s_out f32 [128][68] aliases 0..34816
#define S_SMEM 52224
__global__ void __launch_bounds__(256, 3)
k_shrink(const float* __restrict__ beta, const float* __restrict__ x, float* __restrict__ out) {
    extern __shared__ char sb[];
    uint32_t sbu = smem_u32(sb);
    int t = threadIdx.x, wid = t >> 5, lane = t & 31;
    int b = blockIdx.y, p0 = blockIdx.x * 64;
    const __half* gz = g_gelu + ((size_t)b * HW + p0) * CEn;
    float acc[8][4];
    #pragma unroll
    for (int n = 0; n < 8; n++) acc[n][0] = acc[n][1] = acc[n][2] = acc[n][3] = 0.f;
    uint32_t aA = sbu + 17408 + (wid * 16 + (lane & 15)) * 272 + (lane >> 4) * 16;
    uint32_t aB = sbu + ((lane & 7) + ((lane >> 4) & 1) * 8) * 272 + ((lane >> 3) & 1) * 16;
    for (int kt = 0; kt < 4; kt++) {
        __syncthreads();
        // A chunk
        const uint4* s0 = (const uint4*)g_wsa;
        #pragma unroll
        for (int i = 0; i < 8; i++) {
            int idx = t + i * 256;
            int r = idx >> 4, q = idx & 15;
            uint4 v = s0[r * 64 + kt * 16 + q];
            *(uint4*)(sb + 17408 + r * 272 + q * 16) = v;
        }
        // z tile: a*gelu + beta -> fp16
        #pragma unroll
        for (int i = 0; i < 8; i++) {
            int idx = t + i * 256;
            int p = idx >> 5, q = idx & 31;
            int ce = kt * 128 + q * 4;
            uint2 raw = *(const uint2*)&gz[(size_t)p * CEn + ce];
            __half2 g01 = *(__half2*)&raw.x, g23 = *(__half2*)&raw.y;
            float4 a = *(const float4*)&g_scale[b * CEn + ce];
            float4 bt = *(const float4*)&beta[ce];
            float z0 = a.x * __low2float(g01) + bt.x;
            float z1 = a.y * __high2float(g01) + bt.y;
            float z2 = a.z * __low2float(g23) + bt.z;
            float z3 = a.w * __high2float(g23) + bt.w;
            *(uint2*)(sb + p * 272 + q * 8) = make_uint2(pkh2(z0, z1), pkh2(z2, z3));
        }
        __syncthreads();
        #pragma unroll
        for (int k = 0; k < 8; k++) {
            uint32_t ah[4];
            ldm4(ah, aA + k * 32);
            #pragma unroll
            for (int np = 0; np < 4; np++) {
                uint32_t bh[4];
                ldm4(bh, aB + np * 4352 + k * 32);
                mma_f16(acc[2 * np], ah, bh);
                mma_f16(acc[2 * np + 1], ah, bh + 2);
            }
        }
    }
    __syncthreads();
    float* s_out = (float*)sb;   // [128][68]
    int r0 = wid * 16 + (lane >> 2), cbase = (lane & 3) * 2;
    #pragma unroll
    for (int n = 0; n < 8; n++) {
        int cc = n * 8 + cbase;
        s_out[r0 * 68 + cc] = acc[n][0];
        s_out[r0 * 68 + cc + 1] = acc[n][1];
        s_out[(r0 + 8) * 68 + cc] = acc[n][2];
        s_out[(r0 + 8) * 68 + cc + 1] = acc[n][3];
    }
    __syncthreads();
    const float* xp = x + (size_t)b * Cn * HW + p0;
    float* op = out + (size_t)b * Cn * HW + p0;
    #pragma unroll
    for (int i = 0; i < 8; i++) {
        int idx = t + i * 256, oc = idx >> 4, p4 = (idx & 15) * 4;
        float4 v = *(float4*)&s_out[oc * 68 + p4];
        float4 xv = *(const float4*)&xp[(size_t)oc * HW + p4];
        v.x += xv.x; v.y += xv.y; v.z += xv.z; v.w += xv.w;
        *(float4*)&op[(size_t)oc * HW + p4] = v;
    }
}

// ---------- launch ----------
extern "C" void kernel_launch(void* const* d_in, const int* in_sizes, int n_in,
                              void* d_out, int out_size) {
    const float* x        = (const float*)d_in[0];
    const float* w_fc1    = (const float*)d_in[1];
    const float* ln1_w    = (const float*)d_in[2];
    const float* ln1_b    = (const float*)d_in[3];
    const float* w_fc2    = (const float*)d_in[4];
    const float* ln2_w    = (const float*)d_in[5];
    const float* ln2_b    = (const float*)d_in[6];
    const float* w_expand = (const float*)d_in[7];
    const float* w_shrink = (const float*)d_in[8];
    const float* grn_g    = (const float*)d_in[9];
    const float* grn_b    = (const float*)d_in[10];
    float* out = (float*)d_out;

    cudaFuncSetAttribute(k_expand, cudaFuncAttributeMaxDynamicSharedMemorySize, E_SMEM);
    cudaFuncSetAttribute(k_shrink, cudaFuncAttributeMaxDynamicSharedMemorySize, S_SMEM);

    k_wprep<<<128, 256>>>(w_expand, 0, 6);
    k_wprep<<<128, 256>>>(w_shrink, 1, 8);
    k_zero<<<Bn, CEn>>>();
    k_pool<<<Bn * Cn, 256>>>(x);
    k_fc<<<Bn, 128>>>(w_fc1, ln1_w, ln1_b, w_fc2);
    k_conv<<<Bn * Cn, 256>>>(x);
    k_expand<<<dim3(28, Bn), 256, E_SMEM>>>(ln2_w, ln2_b);
    k_grn<<<Bn, CEn>>>(grn_g);
    k_shrink<<<dim3(49, Bn), 256, S_SMEM>>>(grn_b, x, out);
}

// round 7
// speedup vs baseline: 4.4696x; 1.1188x over previous
#include <cuda_runtime.h>
#include <cuda_fp16.h>
#include <cstdint>
#include <math.h>

#define Bn 32
#define Cn 128
#define Hn 56
#define Wn 56
#define HW 3136
#define CEn 512
#define EPSV 1e-6f

__device__ float g_pooled[Bn * Cn];
__device__ float g_dyn[Bn * Cn * 25];
__device__ __half g_conv[(size_t)Bn * Cn * HW];    // fp16
__device__ __half g_gelu[(size_t)Bn * HW * CEn];   // [b][p][ce] fp16
__device__ float g_sumsq[Bn * CEn];
__device__ float g_scale[Bn * CEn];
__device__ uint32_t g_wea[32768];   // expand W fp16x2 [512][64]
__device__ uint32_t g_wsa[32768];   // shrink W fp16x2 [128][256]

// ---------- helpers ----------
__device__ __forceinline__ uint32_t smem_u32(const void* p) {
    uint32_t a;
    asm("{ .reg .u64 t; cvta.to.shared.u64 t, %1; cvt.u32.u64 %0, t; }" : "=r"(a) : "l"(p));
    return a;
}
__device__ __forceinline__ void ldm4(uint32_t* r, uint32_t a) {
    asm volatile("ldmatrix.sync.aligned.m8n8.x4.shared.b16 {%0,%1,%2,%3}, [%4];"
        : "=r"(r[0]), "=r"(r[1]), "=r"(r[2]), "=r"(r[3]) : "r"(a));
}
__device__ __forceinline__ void mma_f16(float* c, const uint32_t* a, const uint32_t* b) {
    asm volatile("mma.sync.aligned.m16n8k16.row.col.f32.f16.f16.f32 "
        "{%0,%1,%2,%3},{%4,%5,%6,%7},{%8,%9},{%0,%1,%2,%3};"
        : "+f"(c[0]), "+f"(c[1]), "+f"(c[2]), "+f"(c[3])
        : "r"(a[0]), "r"(a[1]), "r"(a[2]), "r"(a[3]), "r"(b[0]), "r"(b[1]));
}
__device__ __forceinline__ uint32_t pkh2(float a, float b) {
    __half2 h = __floats2half2_rn(a, b);
    return *(uint32_t*)&h;
}
__device__ __forceinline__ float gelu_f(float v) { return 0.5f * v * (1.f + erff(v * 0.7071067811865476f)); }

// ---------- weight preconversion (+ sumsq zero) ----------
__global__ void k_wprep(const float* __restrict__ src, int which, int shift) {
    int g = blockIdx.x * 256 + threadIdx.x;         // 32768
    if (g < Bn * CEn) g_sumsq[g] = 0.f;
    int kp = g & ((1 << shift) - 1), row = g >> shift;
    const float* s = src + (size_t)row * (2 << shift) + 2 * kp;
    uint32_t* dst = which ? g_wsa : g_wea;
    dst[(row << shift) + kp] = pkh2(s[0], s[1]);
}

// ---------- small kernels ----------
__global__ void k_pool(const float* __restrict__ x) {
    int bc = blockIdx.x;
    const float* p = x + (size_t)bc * HW;
    float s = 0.f;
    for (int i = threadIdx.x; i < HW / 4; i += 256) {
        float4 v = reinterpret_cast<const float4*>(p)[i];
        s += v.x + v.y + v.z + v.w;
    }
    __shared__ float sm[256];
    sm[threadIdx.x] = s;
    __syncthreads();
    for (int o = 128; o > 0; o >>= 1) {
        if (threadIdx.x < o) sm[threadIdx.x] += sm[threadIdx.x + o];
        __syncthreads();
    }
    if (threadIdx.x == 0) g_pooled[bc] = sm[0] * (1.f / (float)HW);
}

__global__ void k_fc(const float* __restrict__ w_fc1, const float* __restrict__ ln1w,
                     const float* __restrict__ ln1b, const float* __restrict__ w_fc2) {
    int b = blockIdx.x, t = threadIdx.x;
    __shared__ float sp[Cn];
    __shared__ float sh[32];
    sp[t] = g_pooled[b * Cn + t];
    __syncthreads();
    if (t < 32) {
        const float* wr = w_fc1 + t * Cn;
        float a = 0.f;
        #pragma unroll
        for (int i = 0; i < Cn; i++) a += wr[i] * sp[i];
        float u = a;
        #pragma unroll
        for (int o = 16; o > 0; o >>= 1) u += __shfl_xor_sync(~0u, u, o);
        u *= (1.f / 32.f);
        float d = a - u, v = d * d;
        #pragma unroll
        for (int o = 16; o > 0; o >>= 1) v += __shfl_xor_sync(~0u, v, o);
        v *= (1.f / 32.f);
        sh[t] = d * rsqrtf(v + EPSV) * ln1w[t] + ln1b[t];
    }
    __syncthreads();
    for (int i = t; i < Cn * 25; i += 128) {
        const float* wr = w_fc2 + i * 32;
        float a = 0.f;
        #pragma unroll
        for (int j = 0; j < 32; j++) a += wr[j] * sh[j];
        g_dyn[b * Cn * 25 + i] = a;
    }
}

__global__ void k_conv(const float* __restrict__ x) {
    int bc = blockIdx.x;
    __shared__ float tile[60 * 60];
    const float* xp = x + (size_t)bc * HW;
    for (int i = threadIdx.x; i < 3600; i += 256) {
        int r = i / 60, cc = i % 60, h = r - 2, w = cc - 2;
        tile[i] = (h >= 0 && h < Hn && w >= 0 && w < Wn) ? xp[h * Wn + w] : 0.f;
    }
    float kk[25];
    const float* dp = g_dyn + bc * 25;
    #pragma unroll
    for (int i = 0; i < 25; i++) kk[i] = dp[i];
    __syncthreads();
    __half* op = g_conv + (size_t)bc * HW;
    for (int q = threadIdx.x; q < 784; q += 256) {
        int h = q / 14, w0 = (q % 14) * 4;
        float a0 = 0.f, a1 = 0.f, a2 = 0.f, a3 = 0.f;
        #pragma unroll
        for (int i = 0; i < 5; i++) {
            const float* r = &tile[(h + i) * 60 + w0];
            float r0 = r[0], r1 = r[1], r2 = r[2], r3 = r[3];
            float r4 = r[4], r5 = r[5], r6 = r[6], r7 = r[7];
            float k0 = kk[i * 5], k1 = kk[i * 5 + 1], k2 = kk[i * 5 + 2];
            float k3 = kk[i * 5 + 3], k4 = kk[i * 5 + 4];
            a0 += k0 * r0 + k1 * r1 + k2 * r2 + k3 * r3 + k4 * r4;
            a1 += k0 * r1 + k1 * r2 + k2 * r3 + k3 * r4 + k4 * r5;
            a2 += k0 * r2 + k1 * r3 + k2 * r4 + k3 * r5 + k4 * r6;
            a3 += k0 * r3 + k1 * r4 + k2 * r5 + k3 * r6 + k4 * r7;
        }
        *reinterpret_cast<uint2*>(&op[q * 4]) = make_uint2(pkh2(a0, a1), pkh2(a2, a3));
    }
}

// ---------- expand: LN2 + fp16 mma GEMM + gelu + GRN sumsq ----------
// smem: y fp16 [112 px][stride 272B] at 0         (30464)
//       region B at 30720 (34816B), time-shared:
//         stage fp16 [128 c][stride 260B] (33280)
//         A fp16 [128 oc][stride 272B]   (34816)
//         gout fp16 [112 px][stride 264B](29568)
//       misc at 65536: lnw 512, lnb 512, r1 896, r2 896, mu 448, rs 448, s_sq 512
#define E_RB 30720
#define E_SMEM 69760
__global__ void __launch_bounds__(256, 2)
k_expand(const float* __restrict__ ln2w, const float* __restrict__ ln2b) {
    extern __shared__ char sb[];
    uint32_t sbu = smem_u32(sb);
    int t = threadIdx.x, wid = t >> 5, lane = t & 31;
    int b = blockIdx.y, p0 = blockIdx.x * 112;
    float* s_lnw = (float*)(sb + 65536);
    float* s_lnb = (float*)(sb + 66048);
    float* r1 = (float*)(sb + 66560);
    float* r2 = (float*)(sb + 67456);
    float* smu = (float*)(sb + 68352);
    float* srs = (float*)(sb + 68800);
    float* s_sq = (float*)(sb + 69248);
    if (t < 128) { s_lnw[t] = ln2w[t]; s_lnb[t] = ln2b[t]; }
    // load conv tile (fp16) -> stage [c][px], stride 260B: 1792 uint4 (128c x 14)
    const __half* cp = g_conv + (size_t)b * Cn * HW + p0;
    #pragma unroll
    for (int i = 0; i < 7; i++) {
        int idx = t + i * 256;
        int c = idx / 14, qq = idx % 14;
        uint4 v = *(const uint4*)&cp[(size_t)c * HW + qq * 8];
        uint32_t* d = (uint32_t*)(sb + E_RB + c * 260 + qq * 16);
        d[0] = v.x; d[1] = v.y; d[2] = v.z; d[3] = v.w;
    }
    __syncthreads();
    if (t < 224) {
        int p = t % 112, h = t / 112;
        float s = 0.f, s2 = 0.f;
        for (int c = h * 64; c < h * 64 + 64; c++) {
            float v = __half2float(*(__half*)(sb + E_RB + c * 260 + 2 * p));
            s += v; s2 += v * v;
        }
        r1[t] = s; r2[t] = s2;
    }
    __syncthreads();
    if (t < 112) {
        float s = r1[t] + r1[112 + t], s2 = r2[t] + r2[112 + t];
        float mu = s * (1.f / 128.f);
        smu[t] = mu;
        srs[t] = rsqrtf(s2 * (1.f / 128.f) - mu * mu + EPSV);
    }
    __syncthreads();
    // y = LN(conv)*w+b, transposed [px][c], fp16
    #pragma unroll
    for (int i = 0; i < 28; i++) {
        int idx = t + i * 256, p = idx >> 6, cp2 = idx & 63, c0 = cp2 * 2;
        float mu = smu[p], rs = srs[p];
        float x0 = __half2float(*(__half*)(sb + E_RB + c0 * 260 + 2 * p));
        float x1 = __half2float(*(__half*)(sb + E_RB + (c0 + 1) * 260 + 2 * p));
        float v0 = (x0 - mu) * rs * s_lnw[c0] + s_lnb[c0];
        float v1 = (x1 - mu) * rs * s_lnw[c0 + 1] + s_lnb[c0 + 1];
        *(uint32_t*)(sb + p * 272 + cp2 * 4) = pkh2(v0, v1);
    }
    __syncthreads();          // stage dead; y ready
    uint32_t aA = sbu + E_RB + (wid * 16 + (lane & 15)) * 272 + (lane >> 4) * 16;
    uint32_t aB = sbu + ((lane & 7) + ((lane >> 4) & 1) * 8) * 272 + ((lane >> 3) & 1) * 16;
    int r0 = wid * 16 + (lane >> 2), cbase = (lane & 3) * 2;
    uint32_t* gbase = (uint32_t*)g_gelu + ((size_t)b * HW + p0) * 256;
    for (int m = 0; m < 4; m++) {
        if (t < 128) s_sq[t] = 0.f;
        // copy A chunk fp16 into region B
        const uint4* s0 = (const uint4*)g_wea;
        #pragma unroll
        for (int i = 0; i < 8; i++) {
            int idx = t + i * 256;
            int r = idx >> 4, q = idx & 15;
            uint4 v = s0[(m * 128 + r) * 16 + q];
            *(uint4*)(sb + E_RB + r * 272 + q * 16) = v;
        }
        __syncthreads();
        float acc[14][4];
        #pragma unroll
        for (int n = 0; n < 14; n++) { acc[n][0] = acc[n][1] = acc[n][2] = acc[n][3] = 0.f; }
        #pragma unroll
        for (int k = 0; k < 8; k++) {
            uint32_t ah[4];
            ldm4(ah, aA + k * 32);
            #pragma unroll
            for (int np = 0; np < 7; np++) {
                uint32_t bh[4];
                ldm4(bh, aB + np * 4352 + k * 32);
                mma_f16(acc[2 * np], ah, bh);
                mma_f16(acc[2 * np + 1], ah, bh + 2);
            }
        }
        __syncthreads();      // A dead; region B becomes gout [px][oc] stride 264B
        float ss0 = 0.f, ss1 = 0.f;
        #pragma unroll
        for (int n = 0; n < 14; n++) {
            int cc = n * 8 + cbase;
            float g0 = gelu_f(acc[n][0]), g1 = gelu_f(acc[n][1]);
            float g2 = gelu_f(acc[n][2]), g3 = gelu_f(acc[n][3]);
            ss0 += g0 * g0 + g1 * g1;
            ss1 += g2 * g2 + g3 * g3;
            *(__half*)(sb + E_RB + cc * 264 + 2 * r0) = __float2half_rn(g0);
            *(__half*)(sb + E_RB + (cc + 1) * 264 + 2 * r0) = __float2half_rn(g1);
            *(__half*)(sb + E_RB + cc * 264 + 2 * (r0 + 8)) = __float2half_rn(g2);
            *(__half*)(sb + E_RB + (cc + 1) * 264 + 2 * (r0 + 8)) = __float2half_rn(g3);
        }
        atomicAdd(&s_sq[r0], ss0);
        atomicAdd(&s_sq[r0 + 8], ss1);
        __syncthreads();
        if (t < 128) atomicAdd(&g_sumsq[b * CEn + m * 128 + t], s_sq[t]);
        // store pass: coalesced u32 writes to g_gelu
        #pragma unroll
        for (int i = 0; i < 28; i++) {
            int idx = t + i * 256;                 // 7168 u32
            int px = idx >> 6, w = idx & 63;
            uint32_t v = *(uint32_t*)(sb + E_RB + px * 264 + w * 4);
            gbase[(size_t)px * 256 + m * 64 + w] = v;
        }
        __syncthreads();
    }
}

__global__ void k_grn(const float* __restrict__ gamma) {
    int b = blockIdx.x, t = threadIdx.x;
    float gx = sqrtf(g_sumsq[b * CEn + t]);
    __shared__ float sm[CEn];
    sm[t] = gx;
    __syncthreads();
    for (int o = 256; o > 0; o >>= 1) {
        if (t < o) sm[t] += sm[t + o];
        __syncthreads();
    }
    g_scale[b * CEn + t] = gamma[t] * (gx / (sm[0] * (1.f / (float)CEn) + EPSV)) + 1.f;
}

// ---------- shrink: fp16 mma GEMM (scale/beta folded) + residual ----------
// smem: z [64 px][128 ce]fp16 stride 272 at 0 (17408)
//       A [128 oc][128 ce]fp16 stride 272 at 17408 (34816) -> 52224
//       s_out f32 [128][68] aliases 0..34816
#define S_SMEM 52224
__global__ void __launch_bounds__(256, 3)
k_shrink(const float* __restrict__ beta, const float* __restrict__ x, float* __restrict__ out) {
    extern __shared__ char sb[];
    uint32_t sbu = smem_u32(sb);
    int t = threadIdx.x, wid = t >> 5, lane = t & 31;
    int b = blockIdx.y, p0 = blockIdx.x * 64;
    const __half* gz = g_gelu + ((size_t)b * HW + p0) * CEn;
    float acc[8][4];
    #pragma unroll
    for (int n = 0; n < 8; n++) acc[n][0] = acc[n][1] = acc[n][2] = acc[n][3] = 0.f;
    uint32_t aA = sbu + 17408 + (wid * 16 + (lane & 15)) * 272 + (lane >> 4) * 16;
    uint32_t aB = sbu + ((lane & 7) + ((lane >> 4) & 1) * 8) * 272 + ((lane >> 3) & 1) * 16;
    for (int kt = 0; kt < 4; kt++) {
        __syncthreads();
        const uint4* s0 = (const uint4*)g_wsa;
        #pragma unroll
        for (int i = 0; i < 8; i++) {
            int idx = t + i * 256;
            int r = idx >> 4, q = idx & 15;
            uint4 v = s0[r * 64 + kt * 16 + q];
            *(uint4*)(sb + 17408 + r * 272 + q * 16) = v;
        }
        #pragma unroll
        for (int i = 0; i < 8; i++) {
            int idx = t + i * 256;
            int p = idx >> 5, q = idx & 31;
            int ce = kt * 128 + q * 4;
            uint2 raw = *(const uint2*)&gz[(size_t)p * CEn + ce];
            __half2 g01 = *(__half2*)&raw.x, g23 = *(__half2*)&raw.y;
            float4 a = *(const float4*)&g_scale[b * CEn + ce];
            float4 bt = *(const float4*)&beta[ce];
            float z0 = a.x * __low2float(g01) + bt.x;
            float z1 = a.y * __high2float(g01) + bt.y;
            float z2 = a.z * __low2float(g23) + bt.z;
            float z3 = a.w * __high2float(g23) + bt.w;
            *(uint2*)(sb + p * 272 + q * 8) = make_uint2(pkh2(z0, z1), pkh2(z2, z3));
        }
        __syncthreads();
        #pragma unroll
        for (int k = 0; k < 8; k++) {
            uint32_t ah[4];
            ldm4(ah, aA + k * 32);
            #pragma unroll
            for (int np = 0; np < 4; np++) {
                uint32_t bh[4];
                ldm4(bh, aB + np * 4352 + k * 32);
                mma_f16(acc[2 * np], ah, bh);
                mma_f16(acc[2 * np + 1], ah, bh + 2);
            }
        }
    }
    __syncthreads();
    float* s_out = (float*)sb;   // [128][68]
    int r0 = wid * 16 + (lane >> 2), cbase = (lane & 3) * 2;
    #pragma unroll
    for (int n = 0; n < 8; n++) {
        int cc = n * 8 + cbase;
        s_out[r0 * 68 + cc] = acc[n][0];
        s_out[r0 * 68 + cc + 1] = acc[n][1];
        s_out[(r0 + 8) * 68 + cc] = acc[n][2];
        s_out[(r0 + 8) * 68 + cc + 1] = acc[n][3];
    }
    __syncthreads();
    const float* xp = x + (size_t)b * Cn * HW + p0;
    float* op = out + (size_t)b * Cn * HW + p0;
    #pragma unroll
    for (int i = 0; i < 8; i++) {
        int idx = t + i * 256, oc = idx >> 4, p4 = (idx & 15) * 4;
        float4 v = *(float4*)&s_out[oc * 68 + p4];
        float4 xv = *(const float4*)&xp[(size_t)oc * HW + p4];
        v.x += xv.x; v.y += xv.y; v.z += xv.z; v.w += xv.w;
        *(float4*)&op[(size_t)oc * HW + p4] = v;
    }
}

// ---------- launch ----------
extern "C" void kernel_launch(void* const* d_in, const int* in_sizes, int n_in,
                              void* d_out, int out_size) {
    const float* x        = (const float*)d_in[0];
    const float* w_fc1    = (const float*)d_in[1];
    const float* ln1_w    = (const float*)d_in[2];
    const float* ln1_b    = (const float*)d_in[3];
    const float* w_fc2    = (const float*)d_in[4];
    const float* ln2_w    = (const float*)d_in[5];
    const float* ln2_b    = (const float*)d_in[6];
    const float* w_expand = (const float*)d_in[7];
    const float* w_shrink = (const float*)d_in[8];
    const float* grn_g    = (const float*)d_in[9];
    const float* grn_b    = (const float*)d_in[10];
    float* out = (float*)d_out;

    cudaFuncSetAttribute(k_expand, cudaFuncAttributeMaxDynamicSharedMemorySize, E_SMEM);
    cudaFuncSetAttribute(k_shrink, cudaFuncAttributeMaxDynamicSharedMemorySize, S_SMEM);

    k_wprep<<<128, 256>>>(w_expand, 0, 6);
    k_wprep<<<128, 256>>>(w_shrink, 1, 8);
    k_pool<<<Bn * Cn, 256>>>(x);
    k_fc<<<Bn, 128>>>(w_fc1, ln1_w, ln1_b, w_fc2);
    k_conv<<<Bn * Cn, 256>>>(x);
    k_expand<<<dim3(28, Bn), 256, E_SMEM>>>(ln2_w, ln2_b);
    k_grn<<<Bn, CEn>>>(grn_g);
    k_shrink<<<dim3(49, Bn), 256, S_SMEM>>>(grn_b, x, out);
}

// round 9
// speedup vs baseline: 4.9097x; 1.0985x over previous
#include <cuda_runtime.h>
#include <cuda_fp16.h>
#include <cstdint>
#include <math.h>

#define Bn 32
#define Cn 128
#define Hn 56
#define Wn 56
#define HW 3136
#define CEn 512
#define EPSV 1e-6f

__device__ float g_hdn[Bn * 32];
__device__ float g_pooled[Bn * Cn];
__device__ float g_dyn[Bn * Cn * 25];
__device__ __half g_conv[(size_t)Bn * Cn * HW];    // fp16
__device__ __half g_gelu[(size_t)Bn * HW * CEn];   // [b][p][ce] fp16
__device__ float g_sumsq[Bn * CEn];
__device__ float g_scale[Bn * CEn];
__device__ uint32_t g_wea[32768];   // expand W fp16x2 [512][64]
__device__ uint32_t g_wsa[32768];   // shrink W fp16x2 [128][256]

// ---------- helpers ----------
__device__ __forceinline__ uint32_t smem_u32(const void* p) {
    uint32_t a;
    asm("{ .reg .u64 t; cvta.to.shared.u64 t, %1; cvt.u32.u64 %0, t; }" : "=r"(a) : "l"(p));
    return a;
}
__device__ __forceinline__ void ldm4(uint32_t* r, uint32_t a) {
    asm volatile("ldmatrix.sync.aligned.m8n8.x4.shared.b16 {%0,%1,%2,%3}, [%4];"
        : "=r"(r[0]), "=r"(r[1]), "=r"(r[2]), "=r"(r[3]) : "r"(a));
}
__device__ __forceinline__ void mma_f16(float* c, const uint32_t* a, const uint32_t* b) {
    asm volatile("mma.sync.aligned.m16n8k16.row.col.f32.f16.f16.f32 "
        "{%0,%1,%2,%3},{%4,%5,%6,%7},{%8,%9},{%0,%1,%2,%3};"
        : "+f"(c[0]), "+f"(c[1]), "+f"(c[2]), "+f"(c[3])
        : "r"(a[0]), "r"(a[1]), "r"(a[2]), "r"(a[3]), "r"(b[0]), "r"(b[1]));
}
__device__ __forceinline__ uint32_t pkh2(float a, float b) {
    __half2 h = __floats2half2_rn(a, b);
    return *(uint32_t*)&h;
}
__device__ __forceinline__ float gelu_f(float v) { return 0.5f * v * (1.f + erff(v * 0.7071067811865476f)); }

// ---------- weight preconversion (+ sumsq zero) ----------
__global__ void k_wprep(const float* __restrict__ src, int which, int shift) {
    int g = blockIdx.x * 256 + threadIdx.x;         // 32768
    if (g < Bn * CEn) g_sumsq[g] = 0.f;
    int kp = g & ((1 << shift) - 1), row = g >> shift;
    const float* s = src + (size_t)row * (2 << shift) + 2 * kp;
    uint32_t* dst = which ? g_wsa : g_wea;
    dst[(row << shift) + kp] = pkh2(s[0], s[1]);
}

// ---------- small kernels ----------
__global__ void k_pool(const float* __restrict__ x) {
    int bc = blockIdx.x;
    const float* p = x + (size_t)bc * HW;
    int t = threadIdx.x, lane = t & 31, wid = t >> 5;
    float s = 0.f;
    for (int i = t; i < HW / 4; i += 256) {
        float4 v = reinterpret_cast<const float4*>(p)[i];
        s += v.x + v.y + v.z + v.w;
    }
    #pragma unroll
    for (int o = 16; o > 0; o >>= 1) s += __shfl_xor_sync(~0u, s, o);
    __shared__ float sm[8];
    if (lane == 0) sm[wid] = s;
    __syncthreads();
    if (t == 0) {
        float a = 0.f;
        #pragma unroll
        for (int i = 0; i < 8; i++) a += sm[i];
        g_pooled[bc] = a * (1.f / (float)HW);
    }
}

__global__ void k_fc1(const float* __restrict__ w_fc1, const float* __restrict__ ln1w,
                      const float* __restrict__ ln1b) {
    int b = blockIdx.x, t = threadIdx.x;   // 32 threads
    const float* sp = g_pooled + b * Cn;
    const float* wr = w_fc1 + t * Cn;
    float a = 0.f;
    #pragma unroll
    for (int i = 0; i < Cn; i++) a += wr[i] * sp[i];
    float u = a;
    #pragma unroll
    for (int o = 16; o > 0; o >>= 1) u += __shfl_xor_sync(~0u, u, o);
    u *= (1.f / 32.f);
    float d = a - u, v = d * d;
    #pragma unroll
    for (int o = 16; o > 0; o >>= 1) v += __shfl_xor_sync(~0u, v, o);
    v *= (1.f / 32.f);
    g_hdn[b * 32 + t] = d * rsqrtf(v + EPSV) * ln1w[t] + ln1b[t];
}

__global__ void k_fc2(const float* __restrict__ w_fc2) {
    int b = blockIdx.y, t = threadIdx.x;
    int i = blockIdx.x * 256 + t;          // 0..3327, valid < 3200
    __shared__ float sh[32];
    if (t < 32) sh[t] = g_hdn[b * 32 + t];
    __syncthreads();
    if (i < Cn * 25) {
        const float* wr = w_fc2 + i * 32;
        float a = 0.f;
        #pragma unroll
        for (int j = 0; j < 32; j++) a += wr[j] * sh[j];
        g_dyn[b * Cn * 25 + i] = a;
    }
}

__global__ void k_conv(const float* __restrict__ x) {
    int bc = blockIdx.x;
    __shared__ float tile[60 * 60];
    const float* xp = x + (size_t)bc * HW;
    for (int i = threadIdx.x; i < 3600; i += 256) {
        int r = i / 60, cc = i % 60, h = r - 2, w = cc - 2;
        tile[i] = (h >= 0 && h < Hn && w >= 0 && w < Wn) ? xp[h * Wn + w] : 0.f;
    }
    float kk[25];
    const float* dp = g_dyn + bc * 25;
    #pragma unroll
    for (int i = 0; i < 25; i++) kk[i] = dp[i];
    __syncthreads();
    __half* op = g_conv + (size_t)bc * HW;
    for (int q = threadIdx.x; q < 784; q += 256) {
        int h = q / 14, w0 = (q % 14) * 4;
        float a0 = 0.f, a1 = 0.f, a2 = 0.f, a3 = 0.f;
        #pragma unroll
        for (int i = 0; i < 5; i++) {
            const float* r = &tile[(h + i) * 60 + w0];
            float r0 = r[0], r1 = r[1], r2 = r[2], r3 = r[3];
            float r4 = r[4], r5 = r[5], r6 = r[6], r7 = r[7];
            float k0 = kk[i * 5], k1 = kk[i * 5 + 1], k2 = kk[i * 5 + 2];
            float k3 = kk[i * 5 + 3], k4 = kk[i * 5 + 4];
            a0 += k0 * r0 + k1 * r1 + k2 * r2 + k3 * r3 + k4 * r4;
            a1 += k0 * r1 + k1 * r2 + k2 * r3 + k3 * r4 + k4 * r5;
            a2 += k0 * r2 + k1 * r3 + k2 * r4 + k3 * r5 + k4 * r6;
            a3 += k0 * r3 + k1 * r4 + k2 * r5 + k3 * r6 + k4 * r7;
        }
        *reinterpret_cast<uint2*>(&op[q * 4]) = make_uint2(pkh2(a0, a1), pkh2(a2, a3));
    }
}

// ---------- expand: LN2 + fp16 mma GEMM + gelu + GRN sumsq ----------
#define E_RB 30720
#define E_SMEM 69760
__global__ void __launch_bounds__(256, 2)
k_expand(const float* __restrict__ ln2w, const float* __restrict__ ln2b) {
    extern __shared__ char sb[];
    uint32_t sbu = smem_u32(sb);
    int t = threadIdx.x, wid = t >> 5, lane = t & 31;
    int b = blockIdx.y, p0 = blockIdx.x * 112;
    float* s_lnw = (float*)(sb + 65536);
    float* s_lnb = (float*)(sb + 66048);
    float* r1 = (float*)(sb + 66560);
    float* r2 = (float*)(sb + 67456);
    float* smu = (float*)(sb + 68352);
    float* srs = (float*)(sb + 68800);
    float* s_sq = (float*)(sb + 69248);
    if (t < 128) { s_lnw[t] = ln2w[t]; s_lnb[t] = ln2b[t]; }
    const __half* cp = g_conv + (size_t)b * Cn * HW + p0;
    #pragma unroll
    for (int i = 0; i < 7; i++) {
        int idx = t + i * 256;
        int c = idx / 14, qq = idx % 14;
        uint4 v = *(const uint4*)&cp[(size_t)c * HW + qq * 8];
        uint32_t* d = (uint32_t*)(sb + E_RB + c * 260 + qq * 16);
        d[0] = v.x; d[1] = v.y; d[2] = v.z; d[3] = v.w;
    }
    __syncthreads();
    if (t < 224) {
        int p = t % 112, h = t / 112;
        float s = 0.f, s2 = 0.f;
        for (int c = h * 64; c < h * 64 + 64; c++) {
            float v = __half2float(*(__half*)(sb + E_RB + c * 260 + 2 * p));
            s += v; s2 += v * v;
        }
        r1[t] = s; r2[t] = s2;
    }
    __syncthreads();
    if (t < 112) {
        float s = r1[t] + r1[112 + t], s2 = r2[t] + r2[112 + t];
        float mu = s * (1.f / 128.f);
        smu[t] = mu;
        srs[t] = rsqrtf(s2 * (1.f / 128.f) - mu * mu + EPSV);
    }
    __syncthreads();
    #pragma unroll
    for (int i = 0; i < 28; i++) {
        int idx = t + i * 256, p = idx >> 6, cp2 = idx & 63, c0 = cp2 * 2;
        float mu = smu[p], rs = srs[p];
        float x0 = __half2float(*(__half*)(sb + E_RB + c0 * 260 + 2 * p));
        float x1 = __half2float(*(__half*)(sb + E_RB + (c0 + 1) * 260 + 2 * p));
        float v0 = (x0 - mu) * rs * s_lnw[c0] + s_lnb[c0];
        float v1 = (x1 - mu) * rs * s_lnw[c0 + 1] + s_lnb[c0 + 1];
        *(uint32_t*)(sb + p * 272 + cp2 * 4) = pkh2(v0, v1);
    }
    __syncthreads();
    uint32_t aA = sbu + E_RB + (wid * 16 + (lane & 15)) * 272 + (lane >> 4) * 16;
    uint32_t aB = sbu + ((lane & 7) + ((lane >> 4) & 1) * 8) * 272 + ((lane >> 3) & 1) * 16;
    int r0 = wid * 16 + (lane >> 2), cbase = (lane & 3) * 2;
    uint32_t* gbase = (uint32_t*)g_gelu + ((size_t)b * HW + p0) * 256;
    for (int m = 0; m < 4; m++) {
        if (t < 128) s_sq[t] = 0.f;
        const uint4* s0 = (const uint4*)g_wea;
        #pragma unroll
        for (int i = 0; i < 8; i++) {
            int idx = t + i * 256;
            int r = idx >> 4, q = idx & 15;
            uint4 v = s0[(m * 128 + r) * 16 + q];
            *(uint4*)(sb + E_RB + r * 272 + q * 16) = v;
        }
        __syncthreads();
        float acc[14][4];
        #pragma unroll
        for (int n = 0; n < 14; n++) { acc[n][0] = acc[n][1] = acc[n][2] = acc[n][3] = 0.f; }
        #pragma unroll
        for (int k = 0; k < 8; k++) {
            uint32_t ah[4];
            ldm4(ah, aA + k * 32);
            #pragma unroll
            for (int np = 0; np < 7; np++) {
                uint32_t bh[4];
                ldm4(bh, aB + np * 4352 + k * 32);
                mma_f16(acc[2 * np], ah, bh);
                mma_f16(acc[2 * np + 1], ah, bh + 2);
            }
        }
        __syncthreads();
        float ss0 = 0.f, ss1 = 0.f;
        #pragma unroll
        for (int n = 0; n < 14; n++) {
            int cc = n * 8 + cbase;
            float g0 = gelu_f(acc[n][0]), g1 = gelu_f(acc[n][1]);
            float g2 = gelu_f(acc[n][2]), g3 = gelu_f(acc[n][3]);
            ss0 += g0 * g0 + g1 * g1;
            ss1 += g2 * g2 + g3 * g3;
            *(__half*)(sb + E_RB + cc * 264 + 2 * r0) = __float2half_rn(g0);
            *(__half*)(sb + E_RB + (cc + 1) * 264 + 2 * r0) = __float2half_rn(g1);
            *(__half*)(sb + E_RB + cc * 264 + 2 * (r0 + 8)) = __float2half_rn(g2);
            *(__half*)(sb + E_RB + (cc + 1) * 264 + 2 * (r0 + 8)) = __float2half_rn(g3);
        }
        atomicAdd(&s_sq[r0], ss0);
        atomicAdd(&s_sq[r0 + 8], ss1);
        __syncthreads();
        if (t < 128) atomicAdd(&g_sumsq[b * CEn + m * 128 + t], s_sq[t]);
        #pragma unroll
        for (int i = 0; i < 28; i++) {
            int idx = t + i * 256;
            int px = idx >> 6, w = idx & 63;
            uint32_t v = *(uint32_t*)(sb + E_RB + px * 264 + w * 4);
            gbase[(size_t)px * 256 + m * 64 + w] = v;
        }
        __syncthreads();
    }
}

__global__ void k_grn(const float* __restrict__ gamma) {
    int b = blockIdx.x, t = threadIdx.x;
    float gx = sqrtf(g_sumsq[b * CEn + t]);
    __shared__ float sm[CEn];
    sm[t] = gx;
    __syncthreads();
    for (int o = 256; o > 0; o >>= 1) {
        if (t < o) sm[t] += sm[t + o];
        __syncthreads();
    }
    g_scale[b * CEn + t] = gamma[t] * (gx / (sm[0] * (1.f / (float)CEn) + EPSV)) + 1.f;
}

// ---------- shrink: fp16 mma GEMM (scale/beta folded) + residual ----------
#define S_SMEM 52224
__global__ void __launch_bounds__(256, 3)
k_shrink(const float* __restrict__ beta, const float* __restrict__ x, float* __restrict__ out) {
    extern __shared__ char sb[];
    uint32_t sbu = smem_u32(sb);
    int t = threadIdx.x, wid = t >> 5, lane = t & 31;
    int b = blockIdx.y, p0 = blockIdx.x * 64;
    const __half* gz = g_gelu + ((size_t)b * HW + p0) * CEn;
    float acc[8][4];
    #pragma unroll
    for (int n = 0; n < 8; n++) acc[n][0] = acc[n][1] = acc[n][2] = acc[n][3] = 0.f;
    uint32_t aA = sbu + 17408 + (wid * 16 + (lane & 15)) * 272 + (lane >> 4) * 16;
    uint32_t aB = sbu + ((lane & 7) + ((lane >> 4) & 1) * 8) * 272 + ((lane >> 3) & 1) * 16;
    for (int kt = 0; kt < 4; kt++) {
        __syncthreads();
        const uint4* s0 = (const uint4*)g_wsa;
        #pragma unroll
        for (int i = 0; i < 8; i++) {
            int idx = t + i * 256;
            int r = idx >> 4, q = idx & 15;
            uint4 v = s0[r * 64 + kt * 16 + q];
            *(uint4*)(sb + 17408 + r * 272 + q * 16) = v;
        }
        #pragma unroll
        for (int i = 0; i < 8; i++) {
            int idx = t + i * 256;
            int p = idx >> 5, q = idx & 31;
            int ce = kt * 128 + q * 4;
            uint2 raw = *(const uint2*)&gz[(size_t)p * CEn + ce];
            __half2 g01 = *(__half2*)&raw.x, g23 = *(__half2*)&raw.y;
            float4 a = *(const float4*)&g_scale[b * CEn + ce];
            float4 bt = *(const float4*)&beta[ce];
            float z0 = a.x * __low2float(g01) + bt.x;
            float z1 = a.y * __high2float(g01) + bt.y;
            float z2 = a.z * __low2float(g23) + bt.z;
            float z3 = a.w * __high2float(g23) + bt.w;
            *(uint2*)(sb + p * 272 + q * 8) = make_uint2(pkh2(z0, z1), pkh2(z2, z3));
        }
        __syncthreads();
        #pragma unroll
        for (int k = 0; k < 8; k++) {
            uint32_t ah[4];
            ldm4(ah, aA + k * 32);
            #pragma unroll
            for (int np = 0; np < 4; np++) {
                uint32_t bh[4];
                ldm4(bh, aB + np * 4352 + k * 32);
                mma_f16(acc[2 * np], ah, bh);
                mma_f16(acc[2 * np + 1], ah, bh + 2);
            }
        }
    }
    __syncthreads();
    float* s_out = (float*)sb;   // [128][68]
    int r0 = wid * 16 + (lane >> 2), cbase = (lane & 3) * 2;
    #pragma unroll
    for (int n = 0; n < 8; n++) {
        int cc = n * 8 + cbase;
        s_out[r0 * 68 + cc] = acc[n][0];
        s_out[r0 * 68 + cc + 1] = acc[n][1];
        s_out[(r0 + 8) * 68 + cc] = acc[n][2];
        s_out[(r0 + 8) * 68 + cc + 1] = acc[n][3];
    }
    __syncthreads();
    const float* xp = x + (size_t)b * Cn * HW + p0;
    float* op = out + (size_t)b * Cn * HW + p0;
    #pragma unroll
    for (int i = 0; i < 8; i++) {
        int idx = t + i * 256, oc = idx >> 4, p4 = (idx & 15) * 4;
        float4 v = *(float4*)&s_out[oc * 68 + p4];
        float4 xv = *(const float4*)&xp[(size_t)oc * HW + p4];
        v.x += xv.x; v.y += xv.y; v.z += xv.z; v.w += xv.w;
        *(float4*)&op[(size_t)oc * HW + p4] = v;
    }
}

// ---------- launch ----------
extern "C" void kernel_launch(void* const* d_in, const int* in_sizes, int n_in,
                              void* d_out, int out_size) {
    const float* x        = (const float*)d_in[0];
    const float* w_fc1    = (const float*)d_in[1];
    const float* ln1_w    = (const float*)d_in[2];
    const float* ln1_b    = (const float*)d_in[3];
    const float* w_fc2    = (const float*)d_in[4];
    const float* ln2_w    = (const float*)d_in[5];
    const float* ln2_b    = (const float*)d_in[6];
    const float* w_expand = (const float*)d_in[7];
    const float* w_shrink = (const float*)d_in[8];
    const float* grn_g    = (const float*)d_in[9];
    const float* grn_b    = (const float*)d_in[10];
    float* out = (float*)d_out;

    cudaFuncSetAttribute(k_expand, cudaFuncAttributeMaxDynamicSharedMemorySize, E_SMEM);
    cudaFuncSetAttribute(k_shrink, cudaFuncAttributeMaxDynamicSharedMemorySize, S_SMEM);

    k_wprep<<<128, 256>>>(w_expand, 0, 6);
    k_wprep<<<128, 256>>>(w_shrink, 1, 8);
    k_pool<<<Bn * Cn, 256>>>(x);
    k_fc1<<<Bn, 32>>>(w_fc1, ln1_w, ln1_b);
    k_fc2<<<dim3(13, Bn), 256>>>(w_fc2);
    k_conv<<<Bn * Cn, 256>>>(x);
    k_expand<<<dim3(28, Bn), 256, E_SMEM>>>(ln2_w, ln2_b);
    k_grn<<<Bn, CEn>>>(grn_g);
    k_shrink<<<dim3(49, Bn), 256, S_SMEM>>>(grn_b, x, out);
}

// round 10
// speedup vs baseline: 5.1443x; 1.0478x over previous
#include <cuda_runtime.h>
#include <cuda_fp16.h>
#include <cstdint>
#include <math.h>

#define Bn 32
#define Cn 128
#define Hn 56
#define Wn 56
#define HW 3136
#define CEn 512
#define EPSV 1e-6f

__device__ float g_pooled[Bn * Cn];
__device__ float g_dyn[Bn * Cn * 25];
__device__ __half g_conv[(size_t)Bn * Cn * HW];    // fp16
__device__ __half g_gelu[(size_t)Bn * HW * CEn];   // [b][p][ce] fp16
__device__ float g_sumsq[Bn * CEn];
__device__ float g_scale[Bn * CEn];
__device__ uint32_t g_wea[32768];   // expand W fp16x2 [512][64]
__device__ uint32_t g_wsa[32768];   // shrink W fp16x2 [128][256]

// ---------- helpers ----------
__device__ __forceinline__ uint32_t smem_u32(const void* p) {
    uint32_t a;
    asm("{ .reg .u64 t; cvta.to.shared.u64 t, %1; cvt.u32.u64 %0, t; }" : "=r"(a) : "l"(p));
    return a;
}
__device__ __forceinline__ void ldm4(uint32_t* r, uint32_t a) {
    asm volatile("ldmatrix.sync.aligned.m8n8.x4.shared.b16 {%0,%1,%2,%3}, [%4];"
        : "=r"(r[0]), "=r"(r[1]), "=r"(r[2]), "=r"(r[3]) : "r"(a));
}
__device__ __forceinline__ void mma_f16(float* c, const uint32_t* a, const uint32_t* b) {
    asm volatile("mma.sync.aligned.m16n8k16.row.col.f32.f16.f16.f32 "
        "{%0,%1,%2,%3},{%4,%5,%6,%7},{%8,%9},{%0,%1,%2,%3};"
        : "+f"(c[0]), "+f"(c[1]), "+f"(c[2]), "+f"(c[3])
        : "r"(a[0]), "r"(a[1]), "r"(a[2]), "r"(a[3]), "r"(b[0]), "r"(b[1]));
}
__device__ __forceinline__ uint32_t pkh2(float a, float b) {
    __half2 h = __floats2half2_rn(a, b);
    return *(uint32_t*)&h;
}
// Abramowitz-Stegun 7.1.26 erf approximation (abs err <= 1.5e-7)
__device__ __forceinline__ float gelu_f(float v) {
    float z = fabsf(v) * 0.7071067811865476f;
    float t = __fdividef(1.f, fmaf(0.3275911f, z, 1.f));
    float p = t * fmaf(t, fmaf(t, fmaf(t, fmaf(t, 1.061405429f, -1.453152027f),
                1.421413741f), -0.284496736f), 0.254829592f);
    float erfv = 1.f - p * __expf(-z * z);
    erfv = copysignf(erfv, v);
    return 0.5f * v * (1.f + erfv);
}

// ---------- weight preconversion (+ sumsq zero), single launch ----------
__global__ void k_wprep(const float* __restrict__ we, const float* __restrict__ ws) {
    int g = blockIdx.x * 256 + threadIdx.x;         // 65536
    if (g < Bn * CEn) g_sumsq[g] = 0.f;
    int which = g >> 15, r = g & 32767;
    int shift = which ? 8 : 6;
    const float* src = which ? ws : we;
    int kp = r & ((1 << shift) - 1), row = r >> shift;
    const float* s = src + (size_t)row * (2 << shift) + 2 * kp;
    (which ? g_wsa : g_wea)[(row << shift) + kp] = pkh2(s[0], s[1]);
}

// ---------- small kernels ----------
__global__ void k_pool(const float* __restrict__ x) {
    int bc = blockIdx.x;
    const float* p = x + (size_t)bc * HW;
    int t = threadIdx.x, lane = t & 31, wid = t >> 5;
    float s = 0.f;
    for (int i = t; i < HW / 4; i += 256) {
        float4 v = reinterpret_cast<const float4*>(p)[i];
        s += v.x + v.y + v.z + v.w;
    }
    #pragma unroll
    for (int o = 16; o > 0; o >>= 1) s += __shfl_xor_sync(~0u, s, o);
    __shared__ float sm[8];
    if (lane == 0) sm[wid] = s;
    __syncthreads();
    if (t == 0) {
        float a = 0.f;
        #pragma unroll
        for (int i = 0; i < 8; i++) a += sm[i];
        g_pooled[bc] = a * (1.f / (float)HW);
    }
}

// fc1+LN1 (warp 0, redundant per block) then fc2
__global__ void k_fc(const float* __restrict__ w_fc1, const float* __restrict__ ln1w,
                     const float* __restrict__ ln1b, const float* __restrict__ w_fc2) {
    int b = blockIdx.y, t = threadIdx.x;
    __shared__ float sh[32];
    if (t < 32) {
        const float* sp = g_pooled + b * Cn;
        const float* wr = w_fc1 + t * Cn;
        float a = 0.f;
        #pragma unroll
        for (int i = 0; i < Cn; i++) a += wr[i] * sp[i];
        float u = a;
        #pragma unroll
        for (int o = 16; o > 0; o >>= 1) u += __shfl_xor_sync(~0u, u, o);
        u *= (1.f / 32.f);
        float d = a - u, v = d * d;
        #pragma unroll
        for (int o = 16; o > 0; o >>= 1) v += __shfl_xor_sync(~0u, v, o);
        v *= (1.f / 32.f);
        sh[t] = d * rsqrtf(v + EPSV) * ln1w[t] + ln1b[t];
    }
    __syncthreads();
    int i = blockIdx.x * 256 + t;
    if (i < Cn * 25) {
        const float* wr = w_fc2 + i * 32;
        float a = 0.f;
        #pragma unroll
        for (int j = 0; j < 32; j++) a += wr[j] * sh[j];
        g_dyn[b * Cn * 25 + i] = a;
    }
}

__global__ void k_conv(const float* __restrict__ x) {
    int bc = blockIdx.x;
    __shared__ float tile[60 * 60];
    const float* xp = x + (size_t)bc * HW;
    for (int i = threadIdx.x; i < 3600; i += 256) {
        int r = i / 60, cc = i % 60, h = r - 2, w = cc - 2;
        tile[i] = (h >= 0 && h < Hn && w >= 0 && w < Wn) ? xp[h * Wn + w] : 0.f;
    }
    float kk[25];
    const float* dp = g_dyn + bc * 25;
    #pragma unroll
    for (int i = 0; i < 25; i++) kk[i] = dp[i];
    __syncthreads();
    __half* op = g_conv + (size_t)bc * HW;
    for (int q = threadIdx.x; q < 784; q += 256) {
        int h = q / 14, w0 = (q % 14) * 4;
        float a0 = 0.f, a1 = 0.f, a2 = 0.f, a3 = 0.f;
        #pragma unroll
        for (int i = 0; i < 5; i++) {
            const float* r = &tile[(h + i) * 60 + w0];
            float r0 = r[0], r1 = r[1], r2 = r[2], r3 = r[3];
            float r4 = r[4], r5 = r[5], r6 = r[6], r7 = r[7];
            float k0 = kk[i * 5], k1 = kk[i * 5 + 1], k2 = kk[i * 5 + 2];
            float k3 = kk[i * 5 + 3], k4 = kk[i * 5 + 4];
            a0 += k0 * r0 + k1 * r1 + k2 * r2 + k3 * r3 + k4 * r4;
            a1 += k0 * r1 + k1 * r2 + k2 * r3 + k3 * r4 + k4 * r5;
            a2 += k0 * r2 + k1 * r3 + k2 * r4 + k3 * r5 + k4 * r6;
            a3 += k0 * r3 + k1 * r4 + k2 * r5 + k3 * r6 + k4 * r7;
        }
        *reinterpret_cast<uint2*>(&op[q * 4]) = make_uint2(pkh2(a0, a1), pkh2(a2, a3));
    }
}

// ---------- expand: LN2 + fp16 mma GEMM + gelu + GRN sumsq ----------
#define E_RB 30720
#define E_SMEM 69760
__global__ void __launch_bounds__(256, 2)
k_expand(const float* __restrict__ ln2w, const float* __restrict__ ln2b) {
    extern __shared__ char sb[];
    uint32_t sbu = smem_u32(sb);
    int t = threadIdx.x, wid = t >> 5, lane = t & 31;
    int b = blockIdx.y, p0 = blockIdx.x * 112;
    float* s_lnw = (float*)(sb + 65536);
    float* s_lnb = (float*)(sb + 66048);
    float* r1 = (float*)(sb + 66560);
    float* r2 = (float*)(sb + 67456);
    float* smu = (float*)(sb + 68352);
    float* srs = (float*)(sb + 68800);
    float* s_sq = (float*)(sb + 69248);
    if (t < 128) { s_lnw[t] = ln2w[t]; s_lnb[t] = ln2b[t]; }
    const __half* cp = g_conv + (size_t)b * Cn * HW + p0;
    #pragma unroll
    for (int i = 0; i < 7; i++) {
        int idx = t + i * 256;
        int c = idx / 14, qq = idx % 14;
        uint4 v = *(const uint4*)&cp[(size_t)c * HW + qq * 8];
        uint32_t* d = (uint32_t*)(sb + E_RB + c * 260 + qq * 16);
        d[0] = v.x; d[1] = v.y; d[2] = v.z; d[3] = v.w;
    }
    __syncthreads();
    if (t < 224) {
        int p = t % 112, h = t / 112;
        float s = 0.f, s2 = 0.f;
        for (int c = h * 64; c < h * 64 + 64; c++) {
            float v = __half2float(*(__half*)(sb + E_RB + c * 260 + 2 * p));
            s += v; s2 += v * v;
        }
        r1[t] = s; r2[t] = s2;
    }
    __syncthreads();
    if (t < 112) {
        float s = r1[t] + r1[112 + t], s2 = r2[t] + r2[112 + t];
        float mu = s * (1.f / 128.f);
        smu[t] = mu;
        srs[t] = rsqrtf(s2 * (1.f / 128.f) - mu * mu + EPSV);
    }
    __syncthreads();
    #pragma unroll
    for (int i = 0; i < 28; i++) {
        int idx = t + i * 256, p = idx >> 6, cp2 = idx & 63, c0 = cp2 * 2;
        float mu = smu[p], rs = srs[p];
        float x0 = __half2float(*(__half*)(sb + E_RB + c0 * 260 + 2 * p));
        float x1 = __half2float(*(__half*)(sb + E_RB + (c0 + 1) * 260 + 2 * p));
        float v0 = (x0 - mu) * rs * s_lnw[c0] + s_lnb[c0];
        float v1 = (x1 - mu) * rs * s_lnw[c0 + 1] + s_lnb[c0 + 1];
        *(uint32_t*)(sb + p * 272 + cp2 * 4) = pkh2(v0, v1);
    }
    __syncthreads();
    uint32_t aA = sbu + E_RB + (wid * 16 + (lane & 15)) * 272 + (lane >> 4) * 16;
    uint32_t aB = sbu + ((lane & 7) + ((lane >> 4) & 1) * 8) * 272 + ((lane >> 3) & 1) * 16;
    int r0 = wid * 16 + (lane >> 2), cbase = (lane & 3) * 2;
    uint32_t* gbase = (uint32_t*)g_gelu + ((size_t)b * HW + p0) * 256;
    for (int m = 0; m < 4; m++) {
        if (t < 128) s_sq[t] = 0.f;
        const uint4* s0 = (const uint4*)g_wea;
        #pragma unroll
        for (int i = 0; i < 8; i++) {
            int idx = t + i * 256;
            int r = idx >> 4, q = idx & 15;
            uint4 v = s0[(m * 128 + r) * 16 + q];
            *(uint4*)(sb + E_RB + r * 272 + q * 16) = v;
        }
        __syncthreads();
        float acc[14][4];
        #pragma unroll
        for (int n = 0; n < 14; n++) { acc[n][0] = acc[n][1] = acc[n][2] = acc[n][3] = 0.f; }
        #pragma unroll
        for (int k = 0; k < 8; k++) {
            uint32_t ah[4];
            ldm4(ah, aA + k * 32);
            #pragma unroll
            for (int np = 0; np < 7; np++) {
                uint32_t bh[4];
                ldm4(bh, aB + np * 4352 + k * 32);
                mma_f16(acc[2 * np], ah, bh);
                mma_f16(acc[2 * np + 1], ah, bh + 2);
            }
        }
        __syncthreads();
        float ss0 = 0.f, ss1 = 0.f;
        #pragma unroll
        for (int n = 0; n < 14; n++) {
            int cc = n * 8 + cbase;
            float g0 = gelu_f(acc[n][0]), g1 = gelu_f(acc[n][1]);
            float g2 = gelu_f(acc[n][2]), g3 = gelu_f(acc[n][3]);
            ss0 += g0 * g0 + g1 * g1;
            ss1 += g2 * g2 + g3 * g3;
            *(__half*)(sb + E_RB + cc * 264 + 2 * r0) = __float2half_rn(g0);
            *(__half*)(sb + E_RB + (cc + 1) * 264 + 2 * r0) = __float2half_rn(g1);
            *(__half*)(sb + E_RB + cc * 264 + 2 * (r0 + 8)) = __float2half_rn(g2);
            *(__half*)(sb + E_RB + (cc + 1) * 264 + 2 * (r0 + 8)) = __float2half_rn(g3);
        }
        atomicAdd(&s_sq[r0], ss0);
        atomicAdd(&s_sq[r0 + 8], ss1);
        __syncthreads();
        if (t < 128) atomicAdd(&g_sumsq[b * CEn + m * 128 + t], s_sq[t]);
        #pragma unroll
        for (int i = 0; i < 28; i++) {
            int idx = t + i * 256;
            int px = idx >> 6, w = idx & 63;
            uint32_t v = *(uint32_t*)(sb + E_RB + px * 264 + w * 4);
            gbase[(size_t)px * 256 + m * 64 + w] = v;
        }
        __syncthreads();
    }
}

__global__ void k_grn(const float* __restrict__ gamma) {
    int b = blockIdx.x, t = threadIdx.x;
    float gx = sqrtf(g_sumsq[b * CEn + t]);
    __shared__ float sm[CEn];
    sm[t] = gx;
    __syncthreads();
    for (int o = 256; o > 0; o >>= 1) {
        if (t < o) sm[t] += sm[t + o];
        __syncthreads();
    }
    g_scale[b * CEn + t] = gamma[t] * (gx / (sm[0] * (1.f / (float)CEn) + EPSV)) + 1.f;
}

// ---------- shrink: fp16 mma GEMM (scale/beta folded) + residual ----------
#define S_SMEM 52224
__global__ void __launch_bounds__(256, 3)
k_shrink(const float* __restrict__ beta, const float* __restrict__ x, float* __restrict__ out) {
    extern __shared__ char sb[];
    uint32_t sbu = smem_u32(sb);
    int t = threadIdx.x, wid = t >> 5, lane = t & 31;
    int b = blockIdx.y, p0 = blockIdx.x * 64;
    const __half* gz = g_gelu + ((size_t)b * HW + p0) * CEn;
    float acc[8][4];
    #pragma unroll
    for (int n = 0; n < 8; n++) acc[n][0] = acc[n][1] = acc[n][2] = acc[n][3] = 0.f;
    uint32_t aA = sbu + 17408 + (wid * 16 + (lane & 15)) * 272 + (lane >> 4) * 16;
    uint32_t aB = sbu + ((lane & 7) + ((lane >> 4) & 1) * 8) * 272 + ((lane >> 3) & 1) * 16;
    for (int kt = 0; kt < 4; kt++) {
        __syncthreads();
        const uint4* s0 = (const uint4*)g_wsa;
        #pragma unroll
        for (int i = 0; i < 8; i++) {
            int idx = t + i * 256;
            int r = idx >> 4, q = idx & 15;
            uint4 v = s0[r * 64 + kt * 16 + q];
            *(uint4*)(sb + 17408 + r * 272 + q * 16) = v;
        }
        #pragma unroll
        for (int i = 0; i < 8; i++) {
            int idx = t + i * 256;
            int p = idx >> 5, q = idx & 31;
            int ce = kt * 128 + q * 4;
            uint2 raw = *(const uint2*)&gz[(size_t)p * CEn + ce];
            __half2 g01 = *(__half2*)&raw.x, g23 = *(__half2*)&raw.y;
            float4 a = *(const float4*)&g_scale[b * CEn + ce];
            float4 bt = *(const float4*)&beta[ce];
            float z0 = a.x * __low2float(g01) + bt.x;
            float z1 = a.y * __high2float(g01) + bt.y;
            float z2 = a.z * __low2float(g23) + bt.z;
            float z3 = a.w * __high2float(g23) + bt.w;
            *(uint2*)(sb + p * 272 + q * 8) = make_uint2(pkh2(z0, z1), pkh2(z2, z3));
        }
        __syncthreads();
        #pragma unroll
        for (int k = 0; k < 8; k++) {
            uint32_t ah[4];
            ldm4(ah, aA + k * 32);
            #pragma unroll
            for (int np = 0; np < 4; np++) {
                uint32_t bh[4];
                ldm4(bh, aB + np * 4352 + k * 32);
                mma_f16(acc[2 * np], ah, bh);
                mma_f16(acc[2 * np + 1], ah, bh + 2);
            }
        }
    }
    __syncthreads();
    float* s_out = (float*)sb;   // [128][68]
    int r0 = wid * 16 + (lane >> 2), cbase = (lane & 3) * 2;
    #pragma unroll
    for (int n = 0; n < 8; n++) {
        int cc = n * 8 + cbase;
        s_out[r0 * 68 + cc] = acc[n][0];
        s_out[r0 * 68 + cc + 1] = acc[n][1];
        s_out[(r0 + 8) * 68 + cc] = acc[n][2];
        s_out[(r0 + 8) * 68 + cc + 1] = acc[n][3];
    }
    __syncthreads();
    const float* xp = x + (size_t)b * Cn * HW + p0;
    float* op = out + (size_t)b * Cn * HW + p0;
    #pragma unroll
    for (int i = 0; i < 8; i++) {
        int idx = t + i * 256, oc = idx >> 4, p4 = (idx & 15) * 4;
        float4 v = *(float4*)&s_out[oc * 68 + p4];
        float4 xv = *(const float4*)&xp[(size_t)oc * HW + p4];
        v.x += xv.x; v.y += xv.y; v.z += xv.z; v.w += xv.w;
        *(float4*)&op[(size_t)oc * HW + p4] = v;
    }
}

// ---------- launch ----------
extern "C" void kernel_launch(void* const* d_in, const int* in_sizes, int n_in,
                              void* d_out, int out_size) {
    const float* x        = (const float*)d_in[0];
    const float* w_fc1    = (const float*)d_in[1];
    const float* ln1_w    = (const float*)d_in[2];
    const float* ln1_b    = (const float*)d_in[3];
    const float* w_fc2    = (const float*)d_in[4];
    const float* ln2_w    = (const float*)d_in[5];
    const float* ln2_b    = (const float*)d_in[6];
    const float* w_expand = (const float*)d_in[7];
    const float* w_shrink = (const float*)d_in[8];
    const float* grn_g    = (const float*)d_in[9];
    const float* grn_b    = (const float*)d_in[10];
    float* out = (float*)d_out;

    cudaFuncSetAttribute(k_expand, cudaFuncAttributeMaxDynamicSharedMemorySize, E_SMEM);
    cudaFuncSetAttribute(k_shrink, cudaFuncAttributeMaxDynamicSharedMemorySize, S_SMEM);

    k_wprep<<<256, 256>>>(w_expand, w_shrink);
    k_pool<<<Bn * Cn, 256>>>(x);
    k_fc<<<dim3(13, Bn), 256>>>(w_fc1, ln1_w, ln1_b, w_fc2);
    k_conv<<<Bn * Cn, 256>>>(x);
    k_expand<<<dim3(28, Bn), 256, E_SMEM>>>(ln2_w, ln2_b);
    k_grn<<<Bn, CEn>>>(grn_g);
    k_shrink<<<dim3(49, Bn), 256, S_SMEM>>>(grn_b, x, out);
}